// round 1
// baseline (speedup 1.0000x reference)
#include <cuda_runtime.h>
#include <math.h>

// ---------------------------------------------------------------------------
// AttnBlock: GroupNorm -> Q/K/V proj -> softmax(QK^T * scale) V -> proj -> +res
// B=32, C=512, H=W=32 (S=1024). All fp32.
// Scratch lives in __device__ globals (no allocation anywhere).
// ---------------------------------------------------------------------------

#define BB   32
#define CC   512
#define SS   1024
#define NGRP 32
#define CPG  (CC / NGRP)            // 16 channels per group
#define GELEMS (CPG * SS)           // 16384 elements per (b, group)
#define SCALE_QK 0.044194173824159216f

// Scratch buffers (device globals; allowed by harness rules).
static __device__ float g_h[(size_t)BB * CC * SS];   // h [B,C,S]; reused as o2 [B,S,C]
static __device__ float g_q[(size_t)BB * SS * CC];   // q [B,S,C]
static __device__ float g_k[(size_t)BB * SS * CC];   // k [B,S,C]
static __device__ float g_v[(size_t)BB * SS * CC];   // v [B,S,C]
static __device__ float g_o[(size_t)BB * SS * CC];   // attn out [B,S,C]
static __device__ float g_s[(size_t)BB * SS * SS];   // scores [B,S,S]

// ---------------------------------------------------------------------------
// GroupNorm: per (b, g) mean/var over 16 x 1024 elements, normalize, affine.
// Input/output both in [B, C, S] layout (coalesced both passes).
// ---------------------------------------------------------------------------
__global__ __launch_bounds__(256)
void groupnorm_kernel(const float* __restrict__ x, const float* __restrict__ w,
                      const float* __restrict__ bgn, float* __restrict__ h)
{
    const int b = blockIdx.x >> 5;
    const int g = blockIdx.x & 31;
    const size_t base = ((size_t)b * CC + (size_t)g * CPG) * SS;

    float s = 0.f, s2 = 0.f;
    for (int i = threadIdx.x * 4; i < GELEMS; i += 256 * 4) {
        float4 v4 = *reinterpret_cast<const float4*>(&x[base + i]);
        s  += v4.x + v4.y + v4.z + v4.w;
        s2 += v4.x * v4.x + v4.y * v4.y + v4.z * v4.z + v4.w * v4.w;
    }
    #pragma unroll
    for (int o = 16; o; o >>= 1) {
        s  += __shfl_xor_sync(0xffffffffu, s, o);
        s2 += __shfl_xor_sync(0xffffffffu, s2, o);
    }
    __shared__ float ws[8], ws2[8];
    const int lane = threadIdx.x & 31, wid = threadIdx.x >> 5;
    if (lane == 0) { ws[wid] = s; ws2[wid] = s2; }
    __syncthreads();
    __shared__ float s_mu, s_inv;
    if (threadIdx.x == 0) {
        float ts = 0.f, ts2 = 0.f;
        #pragma unroll
        for (int i = 0; i < 8; i++) { ts += ws[i]; ts2 += ws2[i]; }
        const float mu  = ts * (1.f / GELEMS);
        const float var = ts2 * (1.f / GELEMS) - mu * mu;
        s_mu = mu;
        s_inv = rsqrtf(var + 1e-6f);
    }
    __syncthreads();
    const float mu = s_mu, inv = s_inv;
    for (int i = threadIdx.x; i < GELEMS; i += 256) {
        const int c = (g << 4) + (i >> 10);
        h[base + i] = (x[base + i] - mu) * inv * w[c] + bgn[c];
    }
}

// ---------------------------------------------------------------------------
// Generic batched fp32 GEMM: C[m,n] = alpha * sum_k A[m,k]*B[k,n] + bias[n]
//   A_M_MAJOR: A stored A[k*lda + m]   (else A[m*lda + k])
//   B_TRANS:   B given as W[n,k] -> W[n*ldb + k]   (else B[k*ldb + n])
// Tiles: 128x128x16, 256 threads, 8x8 per thread, float4 everywhere.
// Grid: (N/128, M/128, batch). Dims must divide tiles exactly (they do here).
// ---------------------------------------------------------------------------
template<bool A_M_MAJOR, bool B_TRANS>
__global__ __launch_bounds__(256, 2)
void gemm_kernel(const float* __restrict__ A, const float* __restrict__ B,
                 const float* __restrict__ bias, float* __restrict__ Co,
                 int K, int lda, int ldb, int ldc,
                 long long sA, long long sB, long long sC, float alpha)
{
    constexpr int BM = 128, BN = 128, BK = 16;
    __shared__ float As[BK][BM + 4];
    __shared__ float Bs[BK][BN + 4];

    const int tid = threadIdx.x;
    const int bm = blockIdx.y * BM;
    const int bn = blockIdx.x * BN;
    A  += (size_t)blockIdx.z * sA;
    B  += (size_t)blockIdx.z * sB;
    Co += (size_t)blockIdx.z * sC;

    const int tx = tid & 15, ty = tid >> 4;
    const int tm0 = ty * 8, tn0 = tx * 8;

    float acc[8][8];
    #pragma unroll
    for (int i = 0; i < 8; i++)
        #pragma unroll
        for (int j = 0; j < 8; j++) acc[i][j] = 0.f;

    for (int k0 = 0; k0 < K; k0 += BK) {
        // ---- load A tile into As[k][m] ----
        if (A_M_MAJOR) {
            #pragma unroll
            for (int i = 0; i < 2; i++) {
                const int idx = tid + i * 256;          // 0..511
                const int k = idx >> 5;                 // 0..15
                const int m = (idx & 31) << 2;          // 0..124
                const float4 v4 = *reinterpret_cast<const float4*>(
                    &A[(size_t)(k0 + k) * lda + bm + m]);
                *reinterpret_cast<float4*>(&As[k][m]) = v4;
            }
        } else {
            #pragma unroll
            for (int i = 0; i < 2; i++) {
                const int idx = tid + i * 256;
                const int m = idx >> 2;                 // 0..127
                const int k = (idx & 3) << 2;           // 0..12
                const float4 v4 = *reinterpret_cast<const float4*>(
                    &A[(size_t)(bm + m) * lda + k0 + k]);
                As[k + 0][m] = v4.x; As[k + 1][m] = v4.y;
                As[k + 2][m] = v4.z; As[k + 3][m] = v4.w;
            }
        }
        // ---- load B tile into Bs[k][n] ----
        if (B_TRANS) {
            #pragma unroll
            for (int i = 0; i < 2; i++) {
                const int idx = tid + i * 256;
                const int n = idx >> 2;
                const int k = (idx & 3) << 2;
                const float4 v4 = *reinterpret_cast<const float4*>(
                    &B[(size_t)(bn + n) * ldb + k0 + k]);
                Bs[k + 0][n] = v4.x; Bs[k + 1][n] = v4.y;
                Bs[k + 2][n] = v4.z; Bs[k + 3][n] = v4.w;
            }
        } else {
            #pragma unroll
            for (int i = 0; i < 2; i++) {
                const int idx = tid + i * 256;
                const int k = idx >> 5;
                const int n = (idx & 31) << 2;
                const float4 v4 = *reinterpret_cast<const float4*>(
                    &B[(size_t)(k0 + k) * ldb + bn + n]);
                *reinterpret_cast<float4*>(&Bs[k][n]) = v4;
            }
        }
        __syncthreads();

        #pragma unroll
        for (int kk = 0; kk < BK; kk++) {
            float ra[8], rb[8];
            *reinterpret_cast<float4*>(&ra[0]) = *reinterpret_cast<float4*>(&As[kk][tm0]);
            *reinterpret_cast<float4*>(&ra[4]) = *reinterpret_cast<float4*>(&As[kk][tm0 + 4]);
            *reinterpret_cast<float4*>(&rb[0]) = *reinterpret_cast<float4*>(&Bs[kk][tn0]);
            *reinterpret_cast<float4*>(&rb[4]) = *reinterpret_cast<float4*>(&Bs[kk][tn0 + 4]);
            #pragma unroll
            for (int i = 0; i < 8; i++)
                #pragma unroll
                for (int j = 0; j < 8; j++)
                    acc[i][j] += ra[i] * rb[j];
        }
        __syncthreads();
    }

    float bb[8];
    if (bias) {
        #pragma unroll
        for (int j = 0; j < 8; j++) bb[j] = bias[bn + tn0 + j];
    } else {
        #pragma unroll
        for (int j = 0; j < 8; j++) bb[j] = 0.f;
    }
    #pragma unroll
    for (int i = 0; i < 8; i++) {
        float4 r0, r1;
        r0.x = acc[i][0] * alpha + bb[0];
        r0.y = acc[i][1] * alpha + bb[1];
        r0.z = acc[i][2] * alpha + bb[2];
        r0.w = acc[i][3] * alpha + bb[3];
        r1.x = acc[i][4] * alpha + bb[4];
        r1.y = acc[i][5] * alpha + bb[5];
        r1.z = acc[i][6] * alpha + bb[6];
        r1.w = acc[i][7] * alpha + bb[7];
        float* p = &Co[(size_t)(bm + tm0 + i) * ldc + bn + tn0];
        *reinterpret_cast<float4*>(p)     = r0;
        *reinterpret_cast<float4*>(p + 4) = r1;
    }
}

// ---------------------------------------------------------------------------
// Row softmax over 1024 columns. One block (256 threads x 4 cols) per row.
// ---------------------------------------------------------------------------
__global__ __launch_bounds__(256)
void softmax_kernel(float* __restrict__ s)
{
    float* p = s + (size_t)blockIdx.x * SS;
    float4 v = *reinterpret_cast<float4*>(&p[threadIdx.x * 4]);

    float m = fmaxf(fmaxf(v.x, v.y), fmaxf(v.z, v.w));
    #pragma unroll
    for (int o = 16; o; o >>= 1) m = fmaxf(m, __shfl_xor_sync(0xffffffffu, m, o));
    __shared__ float redm[8], reds[8];
    const int lane = threadIdx.x & 31, wid = threadIdx.x >> 5;
    if (lane == 0) redm[wid] = m;
    __syncthreads();
    float M = redm[0];
    #pragma unroll
    for (int i = 1; i < 8; i++) M = fmaxf(M, redm[i]);

    v.x = expf(v.x - M); v.y = expf(v.y - M);
    v.z = expf(v.z - M); v.w = expf(v.w - M);
    float sum = v.x + v.y + v.z + v.w;
    #pragma unroll
    for (int o = 16; o; o >>= 1) sum += __shfl_xor_sync(0xffffffffu, sum, o);
    if (lane == 0) reds[wid] = sum;
    __syncthreads();
    float T = 0.f;
    #pragma unroll
    for (int i = 0; i < 8; i++) T += reds[i];
    const float inv = 1.f / T;

    v.x *= inv; v.y *= inv; v.z *= inv; v.w *= inv;
    *reinterpret_cast<float4*>(&p[threadIdx.x * 4]) = v;
}

// ---------------------------------------------------------------------------
// Final: out[b,c,s] = o2[b,s,c] + x[b,c,s]   (32x32 smem transpose tiles)
// Grid: (S/32, C/32, B), block (32, 8)
// ---------------------------------------------------------------------------
__global__ __launch_bounds__(256)
void transpose_add_kernel(const float* __restrict__ o2, const float* __restrict__ x,
                          float* __restrict__ out)
{
    __shared__ float t[32][33];
    const int b = blockIdx.z;
    const int s0 = blockIdx.x * 32;
    const int c0 = blockIdx.y * 32;

    #pragma unroll
    for (int i = threadIdx.y; i < 32; i += 8)
        t[i][threadIdx.x] = o2[((size_t)b * SS + s0 + i) * CC + c0 + threadIdx.x];
    __syncthreads();
    #pragma unroll
    for (int i = threadIdx.y; i < 32; i += 8) {
        const int c = c0 + i;
        const size_t idx = ((size_t)b * CC + c) * SS + s0 + threadIdx.x;
        out[idx] = t[threadIdx.x][i] + x[idx];
    }
}

// ---------------------------------------------------------------------------
// Launch
// ---------------------------------------------------------------------------
extern "C" void kernel_launch(void* const* d_in, const int* in_sizes, int n_in,
                              void* d_out, int out_size)
{
    const float* x   = (const float*)d_in[0];
    const float* gnw = (const float*)d_in[1];
    const float* gnb = (const float*)d_in[2];
    const float* Wq  = (const float*)d_in[3];
    const float* bq  = (const float*)d_in[4];
    const float* Wk  = (const float*)d_in[5];
    const float* bk  = (const float*)d_in[6];
    const float* Wv  = (const float*)d_in[7];
    const float* bv  = (const float*)d_in[8];
    const float* Wo  = (const float*)d_in[9];
    const float* bo  = (const float*)d_in[10];
    float* out = (float*)d_out;

    float *h, *qb, *kb, *vb, *ob, *sc;
    cudaGetSymbolAddress((void**)&h,  g_h);
    cudaGetSymbolAddress((void**)&qb, g_q);
    cudaGetSymbolAddress((void**)&kb, g_k);
    cudaGetSymbolAddress((void**)&vb, g_v);
    cudaGetSymbolAddress((void**)&ob, g_o);
    cudaGetSymbolAddress((void**)&sc, g_s);

    const long long sSC = (long long)SS * CC;   // per-batch stride, [S,C] buffers
    const long long sSS = (long long)SS * SS;   // per-batch stride, scores
    const long long sCS = (long long)CC * SS;   // per-batch stride, [C,S] buffers

    // 1) GroupNorm (h in [B,C,S])
    groupnorm_kernel<<<BB * NGRP, 256>>>(x, gnw, gnb, h);

    // 2) QKV projections: q[b,s,c] = sum_k h[b,k,s] * W[c,k] + b[c]
    //    A M-major (lda = S), W K-major (ldb = C)
    dim3 gqkv(CC / 128, SS / 128, BB);
    gemm_kernel<true, true><<<gqkv, 256>>>(h, Wq, bq, qb, CC, SS, CC, CC, sCS, 0, sSC, 1.f);
    gemm_kernel<true, true><<<gqkv, 256>>>(h, Wk, bk, kb, CC, SS, CC, CC, sCS, 0, sSC, 1.f);
    gemm_kernel<true, true><<<gqkv, 256>>>(h, Wv, bv, vb, CC, SS, CC, CC, sCS, 0, sSC, 1.f);

    // 3) scores[b,s,t] = SCALE * sum_c q[b,s,c] * k[b,t,c]
    dim3 gsc(SS / 128, SS / 128, BB);
    gemm_kernel<false, true><<<gsc, 256>>>(qb, kb, nullptr, sc, CC, CC, CC, SS,
                                           sSC, sSC, sSS, SCALE_QK);

    // 4) softmax over t
    softmax_kernel<<<BB * SS, 256>>>(sc);

    // 5) o[b,s,c] = sum_t P[b,s,t] * v[b,t,c]   (B in NN layout)
    dim3 gpv(CC / 128, SS / 128, BB);
    gemm_kernel<false, false><<<gpv, 256>>>(sc, vb, nullptr, ob, SS, SS, CC, CC,
                                            sSS, sSC, sSC, 1.f);

    // 6) o2 = o @ Wo^T + bo  (writes into g_h, now free)
    gemm_kernel<false, true><<<gpv, 256>>>(ob, Wo, bo, h, CC, CC, CC, CC,
                                           sSC, 0, sSC, 1.f);

    // 7) out[b,c,s] = o2[b,s,c] + x[b,c,s]
    dim3 gta(SS / 32, CC / 32, BB);
    transpose_add_kernel<<<gta, dim3(32, 8)>>>(h, x, out);
}

// round 4
// speedup vs baseline: 2.0259x; 2.0259x over previous
#include <cuda_runtime.h>
#include <cuda_bf16.h>
#include <math.h>
#include <stdint.h>

// ---------------------------------------------------------------------------
// AttnBlock via mma.sync (HMMA, base sm_100 target — tcgen05 needs sm_100a
// which the harness toolchain does not emit).
// GEMMs: bf16 hi+lo split, 3 passes (hi*hi + hi*lo + lo*hi), fp32 accum.
// ---------------------------------------------------------------------------

#define BB   32
#define CC   512
#define SS   1024
#define NGRP 32
#define CPG  16
#define GELEMS (CPG * SS)
#define SCALE_QK 0.044194173824159216f

typedef __nv_bfloat16 bf16;

// ------------------------------- scratch ----------------------------------
static __device__ float2 g_stats[BB * NGRP];
static __device__ bf16 g_th [(size_t)BB * SS * CC];
static __device__ bf16 g_tl [(size_t)BB * SS * CC];
static __device__ bf16 g_qh [(size_t)BB * SS * CC];
static __device__ bf16 g_ql [(size_t)BB * SS * CC];
static __device__ bf16 g_kh [(size_t)BB * SS * CC];
static __device__ bf16 g_kl [(size_t)BB * SS * CC];
static __device__ bf16 g_vh [(size_t)BB * SS * CC];
static __device__ bf16 g_vl [(size_t)BB * SS * CC];
static __device__ bf16 g_vth[(size_t)BB * CC * SS];
static __device__ bf16 g_vtl[(size_t)BB * CC * SS];
static __device__ float g_s [(size_t)BB * SS * SS];
static __device__ bf16 g_ph [(size_t)BB * SS * SS];
static __device__ bf16 g_pl [(size_t)BB * SS * SS];
static __device__ bf16 g_oh [(size_t)BB * SS * CC];
static __device__ bf16 g_ol [(size_t)BB * SS * CC];
static __device__ float g_o2[(size_t)BB * SS * CC];
static __device__ bf16 g_wh [4 * CC * CC];
static __device__ bf16 g_wl [4 * CC * CC];

// ------------------------------ asm helpers --------------------------------
__device__ __forceinline__ uint32_t smem_u32(const void* p) {
    uint32_t a;
    asm("{ .reg .u64 t; cvta.to.shared.u64 t, %1; cvt.u32.u64 %0, t; }" : "=r"(a) : "l"(p));
    return a;
}
#define CP16(dst, src) \
    asm volatile("cp.async.cg.shared.global [%0], [%1], 16;" :: "r"(dst), "l"(src))
#define CP_COMMIT() asm volatile("cp.async.commit_group;" ::: "memory")
#define CP_WAIT(n)  asm volatile("cp.async.wait_group %0;" :: "n"(n) : "memory")

#define LDSM4(r0, r1, r2, r3, addr) \
    asm volatile("ldmatrix.sync.aligned.m8n8.x4.shared.b16 {%0,%1,%2,%3}, [%4];" \
        : "=r"(r0), "=r"(r1), "=r"(r2), "=r"(r3) : "r"(addr))

#define MMA_BF16(d, a, b) \
    asm volatile("mma.sync.aligned.m16n8k16.row.col.f32.bf16.bf16.f32 " \
        "{%0,%1,%2,%3}, {%4,%5,%6,%7}, {%8,%9}, {%0,%1,%2,%3};" \
        : "+f"((d)[0]), "+f"((d)[1]), "+f"((d)[2]), "+f"((d)[3]) \
        : "r"((a)[0]), "r"((a)[1]), "r"((a)[2]), "r"((a)[3]), \
          "r"((b)[0]), "r"((b)[1]))

// ---------------------------------------------------------------------------
// Warp-MMA batched GEMM: C[m,n] = alpha * (Ah+Al)[m,:].(Bh+Bl)[n,:] + bias[n]
// A [M,K] row-major, B [N,K] row-major, both bf16 hi/lo pairs.
// CTA tile 128x128, BK=32, 8 warps (4x2), warp tile 32x64.
// OUT_MODE 0: fp32 -> Cf.  OUT_MODE 1: bf16 hi/lo split -> Ch, Cl.
// smem stage: 4 tiles x 128 rows x 40 halves (pad 8) = 40960 B; 2 stages.
// ---------------------------------------------------------------------------
template<int OUT_MODE>
__global__ void __launch_bounds__(256, 1)
gemm_mma(const bf16* __restrict__ Ah, const bf16* __restrict__ Al,
         const bf16* __restrict__ Bh, const bf16* __restrict__ Bl,
         const float* __restrict__ bias,
         float* __restrict__ Cf, bf16* __restrict__ Ch, bf16* __restrict__ Cl,
         int K, int lda, int ldb, int ldc,
         long long sA, long long sB, long long sC, float alpha)
{
    extern __shared__ __align__(16) char smem[];
    const uint32_t sb = smem_u32(smem);
    const int tid = threadIdx.x, wid = tid >> 5, lane = tid & 31;
    const int bm = blockIdx.y * 128, bn = blockIdx.x * 128;

    Ah += (size_t)blockIdx.z * sA;  Al += (size_t)blockIdx.z * sA;
    Bh += (size_t)blockIdx.z * sB;  Bl += (size_t)blockIdx.z * sB;

    // load-stage geometry: idx 0..511 -> row (idx>>2), 16B seg (idx&3)
    const int lrow = tid >> 2;            // rows 0..63 for i=0, +64 for i=1
    const int lseg = tid & 3;

    float acc[2][8][4];
    #pragma unroll
    for (int i = 0; i < 2; i++)
        #pragma unroll
        for (int j = 0; j < 8; j++)
            #pragma unroll
            for (int t = 0; t < 4; t++) acc[i][j][t] = 0.f;

    auto load_stage = [&](int k0, int buf) {
        const uint32_t base = sb + buf * 40960;
        #pragma unroll
        for (int half = 0; half < 2; half++) {
            const int r = lrow + half * 64;
            const uint32_t doff = (uint32_t)(r * 80 + lseg * 16);
            CP16(base +         doff, Ah + (size_t)(bm + r) * lda + k0 + lseg * 8);
            CP16(base + 10240 + doff, Al + (size_t)(bm + r) * lda + k0 + lseg * 8);
            CP16(base + 20480 + doff, Bh + (size_t)(bn + r) * ldb + k0 + lseg * 8);
            CP16(base + 30720 + doff, Bl + (size_t)(bn + r) * ldb + k0 + lseg * 8);
        }
    };

    // fragment address components
    const int m0 = (wid & 3) * 32, n0 = (wid >> 2) * 64;
    const int arow = (lane & 7) + ((lane >> 3) & 1) * 8;   // row within 16x16 A tile
    const int acol = (lane >> 4) * 8;                      // k offset within k16
    const int brow = (lane & 7) + (lane >> 4) * 8;         // row within 16-row B pair
    const int bcol = ((lane >> 3) & 1) * 8;

    load_stage(0, 0);
    CP_COMMIT();

    const int NC = K >> 5;
    for (int c = 0; c < NC; c++) {
        const int buf = c & 1;
        if (c + 1 < NC) {
            load_stage((c + 1) << 5, buf ^ 1);
            CP_COMMIT();
            CP_WAIT(1);
        } else {
            CP_WAIT(0);
        }
        __syncthreads();

        const uint32_t st = sb + buf * 40960;
        #pragma unroll
        for (int kx = 0; kx < 32; kx += 16) {
            uint32_t fa[2][2][4];   // [hi/lo][mtile][4]
            uint32_t fb[2][8][2];   // [hi/lo][ntile][2]
            #pragma unroll
            for (int s = 0; s < 2; s++)
                #pragma unroll
                for (int mt = 0; mt < 2; mt++) {
                    const uint32_t ad = st + s * 10240 +
                        (uint32_t)(((m0 + mt * 16 + arow) * 40 + kx + acol) * 2);
                    LDSM4(fa[s][mt][0], fa[s][mt][1], fa[s][mt][2], fa[s][mt][3], ad);
                }
            #pragma unroll
            for (int s = 0; s < 2; s++)
                #pragma unroll
                for (int p = 0; p < 4; p++) {
                    const uint32_t bd = st + 20480 + s * 10240 +
                        (uint32_t)(((n0 + p * 16 + brow) * 40 + kx + bcol) * 2);
                    LDSM4(fb[s][2*p][0], fb[s][2*p][1], fb[s][2*p+1][0], fb[s][2*p+1][1], bd);
                }
            #pragma unroll
            for (int mt = 0; mt < 2; mt++)
                #pragma unroll
                for (int nt = 0; nt < 8; nt++) {
                    MMA_BF16(acc[mt][nt], fa[0][mt], fb[0][nt]);   // hi*hi
                    MMA_BF16(acc[mt][nt], fa[0][mt], fb[1][nt]);   // hi*lo
                    MMA_BF16(acc[mt][nt], fa[1][mt], fb[0][nt]);   // lo*hi
                }
        }
        __syncthreads();
    }

    // ---- epilogue ----
    #pragma unroll
    for (int mt = 0; mt < 2; mt++) {
        const int gm = bm + m0 + mt * 16 + (lane >> 2);
        #pragma unroll
        for (int nt = 0; nt < 8; nt++) {
            const int gn = bn + n0 + nt * 8 + 2 * (lane & 3);
            const float b0 = bias ? bias[gn]     : 0.f;
            const float b1 = bias ? bias[gn + 1] : 0.f;
            const float* d = acc[mt][nt];
            const float v00 = d[0] * alpha + b0, v01 = d[1] * alpha + b1;
            const float v10 = d[2] * alpha + b0, v11 = d[3] * alpha + b1;
            const size_t r0 = (size_t)blockIdx.z * sC + (size_t)gm * ldc + gn;
            const size_t r1 = r0 + (size_t)8 * ldc;
            if (OUT_MODE == 0) {
                *reinterpret_cast<float2*>(&Cf[r0]) = make_float2(v00, v01);
                *reinterpret_cast<float2*>(&Cf[r1]) = make_float2(v10, v11);
            } else {
                bf16 h00 = __float2bfloat16(v00), h01 = __float2bfloat16(v01);
                bf16 h10 = __float2bfloat16(v10), h11 = __float2bfloat16(v11);
                *reinterpret_cast<__nv_bfloat162*>(&Ch[r0]) = __nv_bfloat162(h00, h01);
                *reinterpret_cast<__nv_bfloat162*>(&Ch[r1]) = __nv_bfloat162(h10, h11);
                *reinterpret_cast<__nv_bfloat162*>(&Cl[r0]) = __nv_bfloat162(
                    __float2bfloat16(v00 - __bfloat162float(h00)),
                    __float2bfloat16(v01 - __bfloat162float(h01)));
                *reinterpret_cast<__nv_bfloat162*>(&Cl[r1]) = __nv_bfloat162(
                    __float2bfloat16(v10 - __bfloat162float(h10)),
                    __float2bfloat16(v11 - __bfloat162float(h11)));
            }
        }
    }
}

// ---------------------------------------------------------------------------
// GroupNorm stats
// ---------------------------------------------------------------------------
__global__ __launch_bounds__(256)
void gn_stats_kernel(const float* __restrict__ x, float2* __restrict__ stats)
{
    const int b = blockIdx.x >> 5, g = blockIdx.x & 31;
    const size_t base = ((size_t)b * CC + (size_t)g * CPG) * SS;
    float s = 0.f, s2 = 0.f;
    for (int i = threadIdx.x * 4; i < GELEMS; i += 1024) {
        float4 v = *reinterpret_cast<const float4*>(&x[base + i]);
        s  += v.x + v.y + v.z + v.w;
        s2 += v.x * v.x + v.y * v.y + v.z * v.z + v.w * v.w;
    }
    #pragma unroll
    for (int o = 16; o; o >>= 1) {
        s  += __shfl_xor_sync(0xffffffffu, s, o);
        s2 += __shfl_xor_sync(0xffffffffu, s2, o);
    }
    __shared__ float ws[8], ws2[8];
    if ((threadIdx.x & 31) == 0) { ws[threadIdx.x >> 5] = s; ws2[threadIdx.x >> 5] = s2; }
    __syncthreads();
    if (threadIdx.x == 0) {
        float ts = 0.f, ts2 = 0.f;
        #pragma unroll
        for (int i = 0; i < 8; i++) { ts += ws[i]; ts2 += ws2[i]; }
        const float mu  = ts * (1.f / GELEMS);
        const float var = ts2 * (1.f / GELEMS) - mu * mu;
        stats[blockIdx.x] = make_float2(mu, rsqrtf(var + 1e-6f));
    }
}

// ---------------------------------------------------------------------------
// Normalize + transpose + split: x[b,c,s] -> t_hi/t_lo [b,s,c]
// ---------------------------------------------------------------------------
__global__ __launch_bounds__(256)
void norm_t_kernel(const float* __restrict__ x, const float2* __restrict__ stats,
                   const float* __restrict__ w, const float* __restrict__ bgn,
                   bf16* __restrict__ th, bf16* __restrict__ tl)
{
    __shared__ float sm[32][33];
    const int b = blockIdx.z, s0 = blockIdx.x * 32, c0 = blockIdx.y * 32;
    const int tx = threadIdx.x, ty = threadIdx.y;
    #pragma unroll
    for (int cy = ty; cy < 32; cy += 8) {
        const int c = c0 + cy;
        const float2 st = stats[b * 32 + (c >> 4)];
        const float v = x[((size_t)b * CC + c) * SS + s0 + tx];
        sm[cy][tx] = (v - st.x) * st.y * w[c] + bgn[c];
    }
    __syncthreads();
    #pragma unroll
    for (int sy = ty; sy < 32; sy += 8) {
        const float v = sm[tx][sy];
        const bf16 hi = __float2bfloat16(v);
        const size_t o = ((size_t)b * SS + s0 + sy) * CC + c0 + tx;
        th[o] = hi;
        tl[o] = __float2bfloat16(v - __bfloat162float(hi));
    }
}

// ---------------------------------------------------------------------------
// Transpose v [b,s,c] -> vT [b,c,s]
// ---------------------------------------------------------------------------
__global__ __launch_bounds__(256)
void vt_kernel(const bf16* __restrict__ vh, const bf16* __restrict__ vl,
               bf16* __restrict__ vth, bf16* __restrict__ vtl)
{
    __shared__ bf16 sh[32][33], sl[32][33];
    const int b = blockIdx.z, s0 = blockIdx.x * 32, c0 = blockIdx.y * 32;
    const int tx = threadIdx.x, ty = threadIdx.y;
    #pragma unroll
    for (int sy = ty; sy < 32; sy += 8) {
        const size_t i = ((size_t)b * SS + s0 + sy) * CC + c0 + tx;
        sh[sy][tx] = vh[i];
        sl[sy][tx] = vl[i];
    }
    __syncthreads();
    #pragma unroll
    for (int cy = ty; cy < 32; cy += 8) {
        const size_t o = ((size_t)b * CC + c0 + cy) * SS + s0 + tx;
        vth[o] = sh[tx][cy];
        vtl[o] = sl[tx][cy];
    }
}

// ---------------------------------------------------------------------------
// Row softmax over 1024 cols; P -> bf16 hi/lo
// ---------------------------------------------------------------------------
__global__ __launch_bounds__(256)
void softmax_kernel(const float* __restrict__ s, bf16* __restrict__ ph, bf16* __restrict__ pl)
{
    const size_t ro = (size_t)blockIdx.x * SS;
    float4 v = *reinterpret_cast<const float4*>(&s[ro + threadIdx.x * 4]);

    float m = fmaxf(fmaxf(v.x, v.y), fmaxf(v.z, v.w));
    #pragma unroll
    for (int o = 16; o; o >>= 1) m = fmaxf(m, __shfl_xor_sync(0xffffffffu, m, o));
    __shared__ float redm[8], reds[8];
    const int lane = threadIdx.x & 31, wid = threadIdx.x >> 5;
    if (lane == 0) redm[wid] = m;
    __syncthreads();
    float M = redm[0];
    #pragma unroll
    for (int i = 1; i < 8; i++) M = fmaxf(M, redm[i]);

    v.x = expf(v.x - M); v.y = expf(v.y - M);
    v.z = expf(v.z - M); v.w = expf(v.w - M);
    float sum = v.x + v.y + v.z + v.w;
    #pragma unroll
    for (int o = 16; o; o >>= 1) sum += __shfl_xor_sync(0xffffffffu, sum, o);
    if (lane == 0) reds[wid] = sum;
    __syncthreads();
    float T = 0.f;
    #pragma unroll
    for (int i = 0; i < 8; i++) T += reds[i];
    const float inv = 1.f / T;

    float p[4] = {v.x * inv, v.y * inv, v.z * inv, v.w * inv};
    bf16 hi[4], lo[4];
    #pragma unroll
    for (int i = 0; i < 4; i++) {
        hi[i] = __float2bfloat16(p[i]);
        lo[i] = __float2bfloat16(p[i] - __bfloat162float(hi[i]));
    }
    *reinterpret_cast<__nv_bfloat162*>(&ph[ro + threadIdx.x * 4])     = __nv_bfloat162(hi[0], hi[1]);
    *reinterpret_cast<__nv_bfloat162*>(&ph[ro + threadIdx.x * 4 + 2]) = __nv_bfloat162(hi[2], hi[3]);
    *reinterpret_cast<__nv_bfloat162*>(&pl[ro + threadIdx.x * 4])     = __nv_bfloat162(lo[0], lo[1]);
    *reinterpret_cast<__nv_bfloat162*>(&pl[ro + threadIdx.x * 4 + 2]) = __nv_bfloat162(lo[2], lo[3]);
}

// ---------------------------------------------------------------------------
// Weight split fp32 -> bf16 hi/lo
// ---------------------------------------------------------------------------
__global__ __launch_bounds__(256)
void wsplit_kernel(const float* __restrict__ src, bf16* __restrict__ dh, bf16* __restrict__ dl, int n)
{
    for (int i = blockIdx.x * 256 + threadIdx.x; i < n; i += gridDim.x * 256) {
        const float v = src[i];
        const bf16 hi = __float2bfloat16(v);
        dh[i] = hi;
        dl[i] = __float2bfloat16(v - __bfloat162float(hi));
    }
}

// ---------------------------------------------------------------------------
// Final: out[b,c,s] = o2[b,s,c] + x[b,c,s]
// ---------------------------------------------------------------------------
__global__ __launch_bounds__(256)
void transpose_add_kernel(const float* __restrict__ o2, const float* __restrict__ x,
                          float* __restrict__ out)
{
    __shared__ float t[32][33];
    const int b = blockIdx.z, s0 = blockIdx.x * 32, c0 = blockIdx.y * 32;
    #pragma unroll
    for (int i = threadIdx.y; i < 32; i += 8)
        t[i][threadIdx.x] = o2[((size_t)b * SS + s0 + i) * CC + c0 + threadIdx.x];
    __syncthreads();
    #pragma unroll
    for (int i = threadIdx.y; i < 32; i += 8) {
        const size_t idx = ((size_t)b * CC + c0 + i) * SS + s0 + threadIdx.x;
        out[idx] = t[threadIdx.x][i] + x[idx];
    }
}

// ---------------------------------------------------------------------------
// Launch
// ---------------------------------------------------------------------------
extern "C" void kernel_launch(void* const* d_in, const int* in_sizes, int n_in,
                              void* d_out, int out_size)
{
    const float* x   = (const float*)d_in[0];
    const float* gnw = (const float*)d_in[1];
    const float* gnb = (const float*)d_in[2];
    const float* Wq  = (const float*)d_in[3];
    const float* bq  = (const float*)d_in[4];
    const float* Wk  = (const float*)d_in[5];
    const float* bk  = (const float*)d_in[6];
    const float* Wv  = (const float*)d_in[7];
    const float* bv  = (const float*)d_in[8];
    const float* Wo  = (const float*)d_in[9];
    const float* bo  = (const float*)d_in[10];
    float* out = (float*)d_out;

    float2* stats; bf16 *th, *tl, *qh, *ql, *kh, *kl, *vh, *vl, *vth, *vtl, *ph, *pl, *oh, *ol, *wh, *wl;
    float *sc, *o2;
    cudaGetSymbolAddress((void**)&stats, g_stats);
    cudaGetSymbolAddress((void**)&th,  g_th);   cudaGetSymbolAddress((void**)&tl,  g_tl);
    cudaGetSymbolAddress((void**)&qh,  g_qh);   cudaGetSymbolAddress((void**)&ql,  g_ql);
    cudaGetSymbolAddress((void**)&kh,  g_kh);   cudaGetSymbolAddress((void**)&kl,  g_kl);
    cudaGetSymbolAddress((void**)&vh,  g_vh);   cudaGetSymbolAddress((void**)&vl,  g_vl);
    cudaGetSymbolAddress((void**)&vth, g_vth);  cudaGetSymbolAddress((void**)&vtl, g_vtl);
    cudaGetSymbolAddress((void**)&sc,  g_s);
    cudaGetSymbolAddress((void**)&ph,  g_ph);   cudaGetSymbolAddress((void**)&pl,  g_pl);
    cudaGetSymbolAddress((void**)&oh,  g_oh);   cudaGetSymbolAddress((void**)&ol,  g_ol);
    cudaGetSymbolAddress((void**)&o2,  g_o2);
    cudaGetSymbolAddress((void**)&wh,  g_wh);   cudaGetSymbolAddress((void**)&wl,  g_wl);

    const int SMEM = 2 * 40960;   // 81920 B
    cudaFuncSetAttribute(gemm_mma<0>, cudaFuncAttributeMaxDynamicSharedMemorySize, SMEM);
    cudaFuncSetAttribute(gemm_mma<1>, cudaFuncAttributeMaxDynamicSharedMemorySize, SMEM);

    const long long sSC = (long long)SS * CC;
    const long long sSS = (long long)SS * SS;

    // 0) weight splits
    wsplit_kernel<<<128, 256>>>(Wq, wh + 0 * CC * CC, wl + 0 * CC * CC, CC * CC);
    wsplit_kernel<<<128, 256>>>(Wk, wh + 1 * CC * CC, wl + 1 * CC * CC, CC * CC);
    wsplit_kernel<<<128, 256>>>(Wv, wh + 2 * CC * CC, wl + 2 * CC * CC, CC * CC);
    wsplit_kernel<<<128, 256>>>(Wo, wh + 3 * CC * CC, wl + 3 * CC * CC, CC * CC);

    // 1) GroupNorm stats + normalize/transpose/split -> t [B,S,C]
    gn_stats_kernel<<<BB * NGRP, 256>>>(x, stats);
    norm_t_kernel<<<dim3(SS / 32, CC / 32, BB), dim3(32, 8)>>>(x, stats, gnw, gnb, th, tl);

    // 2) QKV projections
    dim3 gqkv(CC / 128, SS / 128, BB);
    gemm_mma<1><<<gqkv, 256, SMEM>>>(th, tl, wh + 0 * CC * CC, wl + 0 * CC * CC, bq,
                                     nullptr, qh, ql, CC, CC, CC, CC, sSC, 0, sSC, 1.f);
    gemm_mma<1><<<gqkv, 256, SMEM>>>(th, tl, wh + 1 * CC * CC, wl + 1 * CC * CC, bk,
                                     nullptr, kh, kl, CC, CC, CC, CC, sSC, 0, sSC, 1.f);
    gemm_mma<1><<<gqkv, 256, SMEM>>>(th, tl, wh + 2 * CC * CC, wl + 2 * CC * CC, bv,
                                     nullptr, vh, vl, CC, CC, CC, CC, sSC, 0, sSC, 1.f);

    // 3) v -> vT [B,C,S]
    vt_kernel<<<dim3(SS / 32, CC / 32, BB), dim3(32, 8)>>>(vh, vl, vth, vtl);

    // 4) scores = SCALE * q k^T
    dim3 gsc(SS / 128, SS / 128, BB);
    gemm_mma<0><<<gsc, 256, SMEM>>>(qh, ql, kh, kl, nullptr,
                                    sc, nullptr, nullptr, CC, CC, CC, SS, sSC, sSC, sSS, SCALE_QK);

    // 5) softmax -> P bf16 split
    softmax_kernel<<<BB * SS, 256>>>(sc, ph, pl);

    // 6) o = P v
    dim3 gpv(CC / 128, SS / 128, BB);
    gemm_mma<1><<<gpv, 256, SMEM>>>(ph, pl, vth, vtl, nullptr,
                                    nullptr, oh, ol, SS, SS, SS, CC, sSS, sSC, sSC, 1.f);

    // 7) o2 = o Wo^T + bo
    gemm_mma<0><<<gpv, 256, SMEM>>>(oh, ol, wh + 3 * CC * CC, wl + 3 * CC * CC, bo,
                                    o2, nullptr, nullptr, CC, CC, CC, CC, sSC, 0, sSC, 1.f);

    // 8) out = o2^T + x
    transpose_add_kernel<<<dim3(SS / 32, CC / 32, BB), dim3(32, 8)>>>(o2, x, out);
}

// round 5
// speedup vs baseline: 2.6858x; 1.3257x over previous
#include <cuda_runtime.h>
#include <cuda_fp16.h>
#include <math.h>
#include <stdint.h>

// ---------------------------------------------------------------------------
// AttnBlock via mma.sync HMMA (base sm_100 target; tcgen05 unavailable).
// GEMMs: fp16 2-pass split  C = Ah*Bh + Al*Bh  (A exact to 2^-22, B rounded
// once to fp16 => ~1e-4/GEMM residual, measured chain ~3e-5).
// B-side-only operands (K, V, weights) need no lo component at all.
// ---------------------------------------------------------------------------

#define BB   32
#define CC   512
#define SS   1024
#define NGRP 32
#define CPG  16
#define GELEMS (CPG * SS)
#define SCALE_QK 0.044194173824159216f

typedef __half fp16;

// ------------------------------- scratch ----------------------------------
static __device__ float2 g_stats[BB * NGRP];
static __device__ fp16 g_th [(size_t)BB * SS * CC];
static __device__ fp16 g_tl [(size_t)BB * SS * CC];
static __device__ fp16 g_qh [(size_t)BB * SS * CC];
static __device__ fp16 g_ql [(size_t)BB * SS * CC];
static __device__ fp16 g_kh [(size_t)BB * SS * CC];   // k used only as B: hi only
static __device__ fp16 g_vh [(size_t)BB * SS * CC];   // v used only as B: hi only
static __device__ fp16 g_vth[(size_t)BB * CC * SS];
static __device__ float g_s [(size_t)BB * SS * SS];
static __device__ fp16 g_ph [(size_t)BB * SS * SS];
static __device__ fp16 g_pl [(size_t)BB * SS * SS];
static __device__ fp16 g_oh [(size_t)BB * SS * CC];
static __device__ fp16 g_ol [(size_t)BB * SS * CC];
static __device__ float g_o2[(size_t)BB * SS * CC];
static __device__ fp16 g_wh [4 * CC * CC];            // weights as B: hi only

// ------------------------------ asm helpers --------------------------------
__device__ __forceinline__ uint32_t smem_u32(const void* p) {
    uint32_t a;
    asm("{ .reg .u64 t; cvta.to.shared.u64 t, %1; cvt.u32.u64 %0, t; }" : "=r"(a) : "l"(p));
    return a;
}
#define CP16(dst, src) \
    asm volatile("cp.async.cg.shared.global [%0], [%1], 16;" :: "r"(dst), "l"(src))
#define CP_COMMIT() asm volatile("cp.async.commit_group;" ::: "memory")
#define CP_WAIT(n)  asm volatile("cp.async.wait_group %0;" :: "n"(n) : "memory")

#define LDSM4(r0, r1, r2, r3, addr) \
    asm volatile("ldmatrix.sync.aligned.m8n8.x4.shared.b16 {%0,%1,%2,%3}, [%4];" \
        : "=r"(r0), "=r"(r1), "=r"(r2), "=r"(r3) : "r"(addr))

#define MMA_FP16(d, a, b) \
    asm volatile("mma.sync.aligned.m16n8k16.row.col.f32.f16.f16.f32 " \
        "{%0,%1,%2,%3}, {%4,%5,%6,%7}, {%8,%9}, {%0,%1,%2,%3};" \
        : "+f"((d)[0]), "+f"((d)[1]), "+f"((d)[2]), "+f"((d)[3]) \
        : "r"((a)[0]), "r"((a)[1]), "r"((a)[2]), "r"((a)[3]), \
          "r"((b)[0]), "r"((b)[1]))

// ---------------------------------------------------------------------------
// Warp-MMA batched GEMM: C[m,n] = alpha*((Ah+Al)[m,:] . Bh[n,:]) + bias[n]
// A [M,K] row-major (hi+lo fp16), B [N,K] row-major (hi fp16).
// CTA tile 128x128, BK=32, 8 warps (4x2), warp tile 32x64.
// OUT_MODE 0: fp32 -> Cf.  1: fp16 hi/lo -> Ch, Cl.  2: fp16 hi -> Ch.
// smem stage: 3 tiles x 128 rows x 40 halves (pad 8) = 30720 B; 3 stages.
// ---------------------------------------------------------------------------
#define STAGE_B 30720

template<int OUT_MODE>
__global__ void __launch_bounds__(256, 1)
gemm_mma(const fp16* __restrict__ Ah, const fp16* __restrict__ Al,
         const fp16* __restrict__ Bh,
         const float* __restrict__ bias,
         float* __restrict__ Cf, fp16* __restrict__ Ch, fp16* __restrict__ Cl,
         int K, int lda, int ldb, int ldc,
         long long sA, long long sB, long long sC, float alpha)
{
    extern __shared__ __align__(16) char smem[];
    const uint32_t sb = smem_u32(smem);
    const int tid = threadIdx.x, wid = tid >> 5, lane = tid & 31;
    const int bm = blockIdx.y * 128, bn = blockIdx.x * 128;

    Ah += (size_t)blockIdx.z * sA;  Al += (size_t)blockIdx.z * sA;
    Bh += (size_t)blockIdx.z * sB;

    const int lrow = tid >> 2;            // 0..63 (+64 second half)
    const int lseg = tid & 3;

    float acc[2][8][4];
    #pragma unroll
    for (int i = 0; i < 2; i++)
        #pragma unroll
        for (int j = 0; j < 8; j++)
            #pragma unroll
            for (int t = 0; t < 4; t++) acc[i][j][t] = 0.f;

    auto load_stage = [&](int k0, int buf) {
        const uint32_t base = sb + buf * STAGE_B;
        #pragma unroll
        for (int half = 0; half < 2; half++) {
            const int r = lrow + half * 64;
            const uint32_t doff = (uint32_t)(r * 80 + lseg * 16);
            CP16(base +         doff, Ah + (size_t)(bm + r) * lda + k0 + lseg * 8);
            CP16(base + 10240 + doff, Al + (size_t)(bm + r) * lda + k0 + lseg * 8);
            CP16(base + 20480 + doff, Bh + (size_t)(bn + r) * ldb + k0 + lseg * 8);
        }
    };

    // fragment address components
    const int m0 = (wid & 3) * 32, n0 = (wid >> 2) * 64;
    const int arow = (lane & 7) + ((lane >> 3) & 1) * 8;
    const int acol = (lane >> 4) * 8;
    const int brow = (lane & 7) + (lane >> 4) * 8;
    const int bcol = ((lane >> 3) & 1) * 8;

    const int NC = K >> 5;
    load_stage(0, 0);
    CP_COMMIT();
    if (NC > 1) { load_stage(32, 1); CP_COMMIT(); }

    for (int c = 0; c < NC; c++) {
        if (c + 1 < NC) { CP_WAIT(1); } else { CP_WAIT(0); }
        __syncthreads();
        if (c + 2 < NC) {
            load_stage((c + 2) << 5, (c + 2) % 3);
            CP_COMMIT();
        }

        const uint32_t st = sb + (c % 3) * STAGE_B;
        #pragma unroll
        for (int kx = 0; kx < 32; kx += 16) {
            uint32_t fa[2][2][4];   // [hi/lo][mtile][4]
            uint32_t fb[8][2];      // [ntile][2]
            #pragma unroll
            for (int s = 0; s < 2; s++)
                #pragma unroll
                for (int mt = 0; mt < 2; mt++) {
                    const uint32_t ad = st + s * 10240 +
                        (uint32_t)(((m0 + mt * 16 + arow) * 40 + kx + acol) * 2);
                    LDSM4(fa[s][mt][0], fa[s][mt][1], fa[s][mt][2], fa[s][mt][3], ad);
                }
            #pragma unroll
            for (int p = 0; p < 4; p++) {
                const uint32_t bd = st + 20480 +
                    (uint32_t)(((n0 + p * 16 + brow) * 40 + kx + bcol) * 2);
                LDSM4(fb[2*p][0], fb[2*p][1], fb[2*p+1][0], fb[2*p+1][1], bd);
            }
            #pragma unroll
            for (int mt = 0; mt < 2; mt++)
                #pragma unroll
                for (int nt = 0; nt < 8; nt++) {
                    MMA_FP16(acc[mt][nt], fa[0][mt], fb[nt]);   // hi*hi
                    MMA_FP16(acc[mt][nt], fa[1][mt], fb[nt]);   // lo*hi
                }
        }
        __syncthreads();
    }

    // ---- epilogue ----
    #pragma unroll
    for (int mt = 0; mt < 2; mt++) {
        const int gm = bm + m0 + mt * 16 + (lane >> 2);
        #pragma unroll
        for (int nt = 0; nt < 8; nt++) {
            const int gn = bn + n0 + nt * 8 + 2 * (lane & 3);
            const float b0 = bias ? bias[gn]     : 0.f;
            const float b1 = bias ? bias[gn + 1] : 0.f;
            const float* d = acc[mt][nt];
            const float v00 = d[0] * alpha + b0, v01 = d[1] * alpha + b1;
            const float v10 = d[2] * alpha + b0, v11 = d[3] * alpha + b1;
            const size_t r0 = (size_t)blockIdx.z * sC + (size_t)gm * ldc + gn;
            const size_t r1 = r0 + (size_t)8 * ldc;
            if (OUT_MODE == 0) {
                *reinterpret_cast<float2*>(&Cf[r0]) = make_float2(v00, v01);
                *reinterpret_cast<float2*>(&Cf[r1]) = make_float2(v10, v11);
            } else {
                const fp16 h00 = __float2half(v00), h01 = __float2half(v01);
                const fp16 h10 = __float2half(v10), h11 = __float2half(v11);
                *reinterpret_cast<__half2*>(&Ch[r0]) = __halves2half2(h00, h01);
                *reinterpret_cast<__half2*>(&Ch[r1]) = __halves2half2(h10, h11);
                if (OUT_MODE == 1) {
                    *reinterpret_cast<__half2*>(&Cl[r0]) = __halves2half2(
                        __float2half(v00 - __half2float(h00)),
                        __float2half(v01 - __half2float(h01)));
                    *reinterpret_cast<__half2*>(&Cl[r1]) = __halves2half2(
                        __float2half(v10 - __half2float(h10)),
                        __float2half(v11 - __half2float(h11)));
                }
            }
        }
    }
}

// ---------------------------------------------------------------------------
// GroupNorm stats
// ---------------------------------------------------------------------------
__global__ __launch_bounds__(256)
void gn_stats_kernel(const float* __restrict__ x, float2* __restrict__ stats)
{
    const int b = blockIdx.x >> 5, g = blockIdx.x & 31;
    const size_t base = ((size_t)b * CC + (size_t)g * CPG) * SS;
    float s = 0.f, s2 = 0.f;
    for (int i = threadIdx.x * 4; i < GELEMS; i += 1024) {
        float4 v = *reinterpret_cast<const float4*>(&x[base + i]);
        s  += v.x + v.y + v.z + v.w;
        s2 += v.x * v.x + v.y * v.y + v.z * v.z + v.w * v.w;
    }
    #pragma unroll
    for (int o = 16; o; o >>= 1) {
        s  += __shfl_xor_sync(0xffffffffu, s, o);
        s2 += __shfl_xor_sync(0xffffffffu, s2, o);
    }
    __shared__ float ws[8], ws2[8];
    if ((threadIdx.x & 31) == 0) { ws[threadIdx.x >> 5] = s; ws2[threadIdx.x >> 5] = s2; }
    __syncthreads();
    if (threadIdx.x == 0) {
        float ts = 0.f, ts2 = 0.f;
        #pragma unroll
        for (int i = 0; i < 8; i++) { ts += ws[i]; ts2 += ws2[i]; }
        const float mu  = ts * (1.f / GELEMS);
        const float var = ts2 * (1.f / GELEMS) - mu * mu;
        stats[blockIdx.x] = make_float2(mu, rsqrtf(var + 1e-6f));
    }
}

// ---------------------------------------------------------------------------
// Normalize + transpose + split: x[b,c,s] -> t_hi/t_lo [b,s,c] fp16
// ---------------------------------------------------------------------------
__global__ __launch_bounds__(256)
void norm_t_kernel(const float* __restrict__ x, const float2* __restrict__ stats,
                   const float* __restrict__ w, const float* __restrict__ bgn,
                   fp16* __restrict__ th, fp16* __restrict__ tl)
{
    __shared__ float sm[32][33];
    const int b = blockIdx.z, s0 = blockIdx.x * 32, c0 = blockIdx.y * 32;
    const int tx = threadIdx.x, ty = threadIdx.y;
    #pragma unroll
    for (int cy = ty; cy < 32; cy += 8) {
        const int c = c0 + cy;
        const float2 st = stats[b * 32 + (c >> 4)];
        const float v = x[((size_t)b * CC + c) * SS + s0 + tx];
        sm[cy][tx] = (v - st.x) * st.y * w[c] + bgn[c];
    }
    __syncthreads();
    #pragma unroll
    for (int sy = ty; sy < 32; sy += 8) {
        const float v = sm[tx][sy];
        const fp16 hi = __float2half(v);
        const size_t o = ((size_t)b * SS + s0 + sy) * CC + c0 + tx;
        th[o] = hi;
        tl[o] = __float2half(v - __half2float(hi));
    }
}

// ---------------------------------------------------------------------------
// Transpose v [b,s,c] -> vT [b,c,s]  (hi only)
// ---------------------------------------------------------------------------
__global__ __launch_bounds__(256)
void vt_kernel(const fp16* __restrict__ vh, fp16* __restrict__ vth)
{
    __shared__ fp16 sh[32][33];
    const int b = blockIdx.z, s0 = blockIdx.x * 32, c0 = blockIdx.y * 32;
    const int tx = threadIdx.x, ty = threadIdx.y;
    #pragma unroll
    for (int sy = ty; sy < 32; sy += 8)
        sh[sy][tx] = vh[((size_t)b * SS + s0 + sy) * CC + c0 + tx];
    __syncthreads();
    #pragma unroll
    for (int cy = ty; cy < 32; cy += 8)
        vth[((size_t)b * CC + c0 + cy) * SS + s0 + tx] = sh[tx][cy];
}

// ---------------------------------------------------------------------------
// Row softmax over 1024 cols; P -> fp16 hi/lo
// ---------------------------------------------------------------------------
__global__ __launch_bounds__(256)
void softmax_kernel(const float* __restrict__ s, fp16* __restrict__ ph, fp16* __restrict__ pl)
{
    const size_t ro = (size_t)blockIdx.x * SS;
    float4 v = *reinterpret_cast<const float4*>(&s[ro + threadIdx.x * 4]);

    float m = fmaxf(fmaxf(v.x, v.y), fmaxf(v.z, v.w));
    #pragma unroll
    for (int o = 16; o; o >>= 1) m = fmaxf(m, __shfl_xor_sync(0xffffffffu, m, o));
    __shared__ float redm[8], reds[8];
    const int lane = threadIdx.x & 31, wid = threadIdx.x >> 5;
    if (lane == 0) redm[wid] = m;
    __syncthreads();
    float M = redm[0];
    #pragma unroll
    for (int i = 1; i < 8; i++) M = fmaxf(M, redm[i]);

    v.x = expf(v.x - M); v.y = expf(v.y - M);
    v.z = expf(v.z - M); v.w = expf(v.w - M);
    float sum = v.x + v.y + v.z + v.w;
    #pragma unroll
    for (int o = 16; o; o >>= 1) sum += __shfl_xor_sync(0xffffffffu, sum, o);
    if (lane == 0) reds[wid] = sum;
    __syncthreads();
    float T = 0.f;
    #pragma unroll
    for (int i = 0; i < 8; i++) T += reds[i];
    const float inv = 1.f / T;

    float p[4] = {v.x * inv, v.y * inv, v.z * inv, v.w * inv};
    fp16 hi[4], lo[4];
    #pragma unroll
    for (int i = 0; i < 4; i++) {
        hi[i] = __float2half(p[i]);
        lo[i] = __float2half(p[i] - __half2float(hi[i]));
    }
    *reinterpret_cast<__half2*>(&ph[ro + threadIdx.x * 4])     = __halves2half2(hi[0], hi[1]);
    *reinterpret_cast<__half2*>(&ph[ro + threadIdx.x * 4 + 2]) = __halves2half2(hi[2], hi[3]);
    *reinterpret_cast<__half2*>(&pl[ro + threadIdx.x * 4])     = __halves2half2(lo[0], lo[1]);
    *reinterpret_cast<__half2*>(&pl[ro + threadIdx.x * 4 + 2]) = __halves2half2(lo[2], lo[3]);
}

// ---------------------------------------------------------------------------
// Weight convert fp32 -> fp16 (B-side only: no lo needed)
// ---------------------------------------------------------------------------
__global__ __launch_bounds__(256)
void wconv_kernel(const float* __restrict__ src, fp16* __restrict__ dh, int n)
{
    for (int i = blockIdx.x * 256 + threadIdx.x; i < n; i += gridDim.x * 256)
        dh[i] = __float2half(src[i]);
}

// ---------------------------------------------------------------------------
// Final: out[b,c,s] = o2[b,s,c] + x[b,c,s]
// ---------------------------------------------------------------------------
__global__ __launch_bounds__(256)
void transpose_add_kernel(const float* __restrict__ o2, const float* __restrict__ x,
                          float* __restrict__ out)
{
    __shared__ float t[32][33];
    const int b = blockIdx.z, s0 = blockIdx.x * 32, c0 = blockIdx.y * 32;
    #pragma unroll
    for (int i = threadIdx.y; i < 32; i += 8)
        t[i][threadIdx.x] = o2[((size_t)b * SS + s0 + i) * CC + c0 + threadIdx.x];
    __syncthreads();
    #pragma unroll
    for (int i = threadIdx.y; i < 32; i += 8) {
        const size_t idx = ((size_t)b * CC + c0 + i) * SS + s0 + threadIdx.x;
        out[idx] = t[threadIdx.x][i] + x[idx];
    }
}

// ---------------------------------------------------------------------------
// Launch
// ---------------------------------------------------------------------------
extern "C" void kernel_launch(void* const* d_in, const int* in_sizes, int n_in,
                              void* d_out, int out_size)
{
    const float* x   = (const float*)d_in[0];
    const float* gnw = (const float*)d_in[1];
    const float* gnb = (const float*)d_in[2];
    const float* Wq  = (const float*)d_in[3];
    const float* bq  = (const float*)d_in[4];
    const float* Wk  = (const float*)d_in[5];
    const float* bk  = (const float*)d_in[6];
    const float* Wv  = (const float*)d_in[7];
    const float* bv  = (const float*)d_in[8];
    const float* Wo  = (const float*)d_in[9];
    const float* bo  = (const float*)d_in[10];
    float* out = (float*)d_out;

    float2* stats; fp16 *th, *tl, *qh, *ql, *kh, *vh, *vth, *ph, *pl, *oh, *ol, *wh;
    float *sc, *o2;
    cudaGetSymbolAddress((void**)&stats, g_stats);
    cudaGetSymbolAddress((void**)&th,  g_th);   cudaGetSymbolAddress((void**)&tl,  g_tl);
    cudaGetSymbolAddress((void**)&qh,  g_qh);   cudaGetSymbolAddress((void**)&ql,  g_ql);
    cudaGetSymbolAddress((void**)&kh,  g_kh);
    cudaGetSymbolAddress((void**)&vh,  g_vh);
    cudaGetSymbolAddress((void**)&vth, g_vth);
    cudaGetSymbolAddress((void**)&sc,  g_s);
    cudaGetSymbolAddress((void**)&ph,  g_ph);   cudaGetSymbolAddress((void**)&pl,  g_pl);
    cudaGetSymbolAddress((void**)&oh,  g_oh);   cudaGetSymbolAddress((void**)&ol,  g_ol);
    cudaGetSymbolAddress((void**)&o2,  g_o2);
    cudaGetSymbolAddress((void**)&wh,  g_wh);

    const int SMEM = 3 * STAGE_B;   // 92160 B
    cudaFuncSetAttribute(gemm_mma<0>, cudaFuncAttributeMaxDynamicSharedMemorySize, SMEM);
    cudaFuncSetAttribute(gemm_mma<1>, cudaFuncAttributeMaxDynamicSharedMemorySize, SMEM);
    cudaFuncSetAttribute(gemm_mma<2>, cudaFuncAttributeMaxDynamicSharedMemorySize, SMEM);

    const long long sSC = (long long)SS * CC;
    const long long sSS = (long long)SS * SS;

    // 0) weight converts (B-side: hi only)
    wconv_kernel<<<64, 256>>>(Wq, wh + 0 * CC * CC, CC * CC);
    wconv_kernel<<<64, 256>>>(Wk, wh + 1 * CC * CC, CC * CC);
    wconv_kernel<<<64, 256>>>(Wv, wh + 2 * CC * CC, CC * CC);
    wconv_kernel<<<64, 256>>>(Wo, wh + 3 * CC * CC, CC * CC);

    // 1) GroupNorm stats + normalize/transpose/split -> t [B,S,C]
    gn_stats_kernel<<<BB * NGRP, 256>>>(x, stats);
    norm_t_kernel<<<dim3(SS / 32, CC / 32, BB), dim3(32, 8)>>>(x, stats, gnw, gnb, th, tl);

    // 2) QKV projections
    dim3 gqkv(CC / 128, SS / 128, BB);
    gemm_mma<1><<<gqkv, 256, SMEM>>>(th, tl, wh + 0 * CC * CC, bq,
                                     nullptr, qh, ql, CC, CC, CC, CC, sSC, 0, sSC, 1.f);
    gemm_mma<2><<<gqkv, 256, SMEM>>>(th, tl, wh + 1 * CC * CC, bk,
                                     nullptr, kh, nullptr, CC, CC, CC, CC, sSC, 0, sSC, 1.f);
    gemm_mma<2><<<gqkv, 256, SMEM>>>(th, tl, wh + 2 * CC * CC, bv,
                                     nullptr, vh, nullptr, CC, CC, CC, CC, sSC, 0, sSC, 1.f);

    // 3) v -> vT [B,C,S]
    vt_kernel<<<dim3(SS / 32, CC / 32, BB), dim3(32, 8)>>>(vh, vth);

    // 4) scores = SCALE * q k^T
    dim3 gsc(SS / 128, SS / 128, BB);
    gemm_mma<0><<<gsc, 256, SMEM>>>(qh, ql, kh, nullptr,
                                    sc, nullptr, nullptr, CC, CC, CC, SS, sSC, sSC, sSS, SCALE_QK);

    // 5) softmax -> P fp16 split
    softmax_kernel<<<BB * SS, 256>>>(sc, ph, pl);

    // 6) o = P v
    dim3 gpv(CC / 128, SS / 128, BB);
    gemm_mma<1><<<gpv, 256, SMEM>>>(ph, pl, vth, nullptr,
                                    nullptr, oh, ol, SS, SS, SS, CC, sSS, sSC, sSC, 1.f);

    // 7) o2 = o Wo^T + bo
    gemm_mma<0><<<gpv, 256, SMEM>>>(oh, ol, wh + 3 * CC * CC, bo,
                                    o2, nullptr, nullptr, CC, CC, CC, CC, sSC, 0, sSC, 1.f);

    // 8) out = o2^T + x
    transpose_add_kernel<<<dim3(SS / 32, CC / 32, BB), dim3(32, 8)>>>(o2, x, out);
}

// round 6
// speedup vs baseline: 4.7628x; 1.7733x over previous
#include <cuda_runtime.h>
#include <cuda_fp16.h>
#include <math.h>
#include <stdint.h>

// ---------------------------------------------------------------------------
// AttnBlock via mma.sync HMMA (base sm_100 target).
// GEMMs: single-pass fp16 (A,B rounded to fp16; fp32 accumulate).
// Calibrated error model: ~4.5e-5 end-to-end (threshold 1e-3).
// ---------------------------------------------------------------------------

#define BB   32
#define CC   512
#define SS   1024
#define NGRP 32
#define CPG  16
#define GELEMS (CPG * SS)
#define SCALE_QK 0.044194173824159216f

typedef __half fp16;

// ------------------------------- scratch ----------------------------------
static __device__ float2 g_stats[BB * NGRP];
static __device__ fp16 g_th [(size_t)BB * SS * CC];
static __device__ fp16 g_qh [(size_t)BB * SS * CC];
static __device__ fp16 g_kh [(size_t)BB * SS * CC];
static __device__ fp16 g_vh [(size_t)BB * SS * CC];
static __device__ fp16 g_vth[(size_t)BB * CC * SS];
static __device__ float g_s [(size_t)BB * SS * SS];
static __device__ fp16 g_ph [(size_t)BB * SS * SS];
static __device__ fp16 g_oh [(size_t)BB * SS * CC];
static __device__ float g_o2[(size_t)BB * SS * CC];
static __device__ fp16 g_wh [4 * CC * CC];

// ------------------------------ asm helpers --------------------------------
__device__ __forceinline__ uint32_t smem_u32(const void* p) {
    uint32_t a;
    asm("{ .reg .u64 t; cvta.to.shared.u64 t, %1; cvt.u32.u64 %0, t; }" : "=r"(a) : "l"(p));
    return a;
}
#define CP16(dst, src) \
    asm volatile("cp.async.cg.shared.global [%0], [%1], 16;" :: "r"(dst), "l"(src))
#define CP_COMMIT() asm volatile("cp.async.commit_group;" ::: "memory")
#define CP_WAIT(n)  asm volatile("cp.async.wait_group %0;" :: "n"(n) : "memory")

#define LDSM4(r0, r1, r2, r3, addr) \
    asm volatile("ldmatrix.sync.aligned.m8n8.x4.shared.b16 {%0,%1,%2,%3}, [%4];" \
        : "=r"(r0), "=r"(r1), "=r"(r2), "=r"(r3) : "r"(addr))

#define MMA_FP16(d, a, b) \
    asm volatile("mma.sync.aligned.m16n8k16.row.col.f32.f16.f16.f32 " \
        "{%0,%1,%2,%3}, {%4,%5,%6,%7}, {%8,%9}, {%0,%1,%2,%3};" \
        : "+f"((d)[0]), "+f"((d)[1]), "+f"((d)[2]), "+f"((d)[3]) \
        : "r"((a)[0]), "r"((a)[1]), "r"((a)[2]), "r"((a)[3]), \
          "r"((b)[0]), "r"((b)[1]))

// ---------------------------------------------------------------------------
// Warp-MMA batched GEMM: C[m,n] = alpha*(A[m,:] . B[n,:]) + bias[n]
// A [M,K] row-major fp16, B [N,K] row-major fp16.
// CTA tile 128x128, BK=32, 8 warps (4x2), warp tile 32x64.
// OUT_MODE 0: fp32 -> Cf.  1: fp16 -> Ch.
// smem stage: 2 tiles x 128 rows x 40 halves (pad 8) = 20480 B; 3 stages.
// ---------------------------------------------------------------------------
#define STAGE_B 20480

template<int OUT_MODE>
__global__ void __launch_bounds__(256, 2)
gemm_mma(const fp16* __restrict__ A, const fp16* __restrict__ B,
         const float* __restrict__ bias,
         float* __restrict__ Cf, fp16* __restrict__ Ch,
         int K, int lda, int ldb, int ldc,
         long long sA, long long sB, long long sC, float alpha)
{
    extern __shared__ __align__(16) char smem[];
    const uint32_t sb = smem_u32(smem);
    const int tid = threadIdx.x, wid = tid >> 5, lane = tid & 31;
    const int bm = blockIdx.y * 128, bn = blockIdx.x * 128;

    A += (size_t)blockIdx.z * sA;
    B += (size_t)blockIdx.z * sB;

    const int lrow = tid >> 2;            // 0..63 (+64 second half)
    const int lseg = tid & 3;

    float acc[2][8][4];
    #pragma unroll
    for (int i = 0; i < 2; i++)
        #pragma unroll
        for (int j = 0; j < 8; j++)
            #pragma unroll
            for (int t = 0; t < 4; t++) acc[i][j][t] = 0.f;

    auto load_stage = [&](int k0, int buf) {
        const uint32_t base = sb + buf * STAGE_B;
        #pragma unroll
        for (int half = 0; half < 2; half++) {
            const int r = lrow + half * 64;
            const uint32_t doff = (uint32_t)(r * 80 + lseg * 16);
            CP16(base +         doff, A + (size_t)(bm + r) * lda + k0 + lseg * 8);
            CP16(base + 10240 + doff, B + (size_t)(bn + r) * ldb + k0 + lseg * 8);
        }
    };

    // fragment address components
    const int m0 = (wid & 3) * 32, n0 = (wid >> 2) * 64;
    const int arow = (lane & 7) + ((lane >> 3) & 1) * 8;
    const int acol = (lane >> 4) * 8;
    const int brow = (lane & 7) + (lane >> 4) * 8;
    const int bcol = ((lane >> 3) & 1) * 8;

    const int NC = K >> 5;
    load_stage(0, 0);
    CP_COMMIT();
    if (NC > 1) { load_stage(32, 1); CP_COMMIT(); }

    for (int c = 0; c < NC; c++) {
        if (c + 1 < NC) { CP_WAIT(1); } else { CP_WAIT(0); }
        __syncthreads();
        if (c + 2 < NC) {
            load_stage((c + 2) << 5, (c + 2) % 3);
            CP_COMMIT();
        }

        const uint32_t st = sb + (c % 3) * STAGE_B;
        #pragma unroll
        for (int kx = 0; kx < 32; kx += 16) {
            uint32_t fa[2][4];      // [mtile][4]
            uint32_t fb[8][2];      // [ntile][2]
            #pragma unroll
            for (int mt = 0; mt < 2; mt++) {
                const uint32_t ad = st +
                    (uint32_t)(((m0 + mt * 16 + arow) * 40 + kx + acol) * 2);
                LDSM4(fa[mt][0], fa[mt][1], fa[mt][2], fa[mt][3], ad);
            }
            #pragma unroll
            for (int p = 0; p < 4; p++) {
                const uint32_t bd = st + 10240 +
                    (uint32_t)(((n0 + p * 16 + brow) * 40 + kx + bcol) * 2);
                LDSM4(fb[2*p][0], fb[2*p][1], fb[2*p+1][0], fb[2*p+1][1], bd);
            }
            #pragma unroll
            for (int mt = 0; mt < 2; mt++)
                #pragma unroll
                for (int nt = 0; nt < 8; nt++)
                    MMA_FP16(acc[mt][nt], fa[mt], fb[nt]);
        }
        __syncthreads();
    }

    // ---- epilogue ----
    #pragma unroll
    for (int mt = 0; mt < 2; mt++) {
        const int gm = bm + m0 + mt * 16 + (lane >> 2);
        #pragma unroll
        for (int nt = 0; nt < 8; nt++) {
            const int gn = bn + n0 + nt * 8 + 2 * (lane & 3);
            const float b0 = bias ? bias[gn]     : 0.f;
            const float b1 = bias ? bias[gn + 1] : 0.f;
            const float* d = acc[mt][nt];
            const float v00 = d[0] * alpha + b0, v01 = d[1] * alpha + b1;
            const float v10 = d[2] * alpha + b0, v11 = d[3] * alpha + b1;
            const size_t r0 = (size_t)blockIdx.z * sC + (size_t)gm * ldc + gn;
            const size_t r1 = r0 + (size_t)8 * ldc;
            if (OUT_MODE == 0) {
                *reinterpret_cast<float2*>(&Cf[r0]) = make_float2(v00, v01);
                *reinterpret_cast<float2*>(&Cf[r1]) = make_float2(v10, v11);
            } else {
                *reinterpret_cast<__half2*>(&Ch[r0]) =
                    __halves2half2(__float2half(v00), __float2half(v01));
                *reinterpret_cast<__half2*>(&Ch[r1]) =
                    __halves2half2(__float2half(v10), __float2half(v11));
            }
        }
    }
}

// ---------------------------------------------------------------------------
// GroupNorm stats
// ---------------------------------------------------------------------------
__global__ __launch_bounds__(256)
void gn_stats_kernel(const float* __restrict__ x, float2* __restrict__ stats)
{
    const int b = blockIdx.x >> 5, g = blockIdx.x & 31;
    const size_t base = ((size_t)b * CC + (size_t)g * CPG) * SS;
    float s = 0.f, s2 = 0.f;
    for (int i = threadIdx.x * 4; i < GELEMS; i += 1024) {
        float4 v = *reinterpret_cast<const float4*>(&x[base + i]);
        s  += v.x + v.y + v.z + v.w;
        s2 += v.x * v.x + v.y * v.y + v.z * v.z + v.w * v.w;
    }
    #pragma unroll
    for (int o = 16; o; o >>= 1) {
        s  += __shfl_xor_sync(0xffffffffu, s, o);
        s2 += __shfl_xor_sync(0xffffffffu, s2, o);
    }
    __shared__ float ws[8], ws2[8];
    if ((threadIdx.x & 31) == 0) { ws[threadIdx.x >> 5] = s; ws2[threadIdx.x >> 5] = s2; }
    __syncthreads();
    if (threadIdx.x == 0) {
        float ts = 0.f, ts2 = 0.f;
        #pragma unroll
        for (int i = 0; i < 8; i++) { ts += ws[i]; ts2 += ws2[i]; }
        const float mu  = ts * (1.f / GELEMS);
        const float var = ts2 * (1.f / GELEMS) - mu * mu;
        stats[blockIdx.x] = make_float2(mu, rsqrtf(var + 1e-6f));
    }
}

// ---------------------------------------------------------------------------
// Normalize + transpose: x[b,c,s] -> t [b,s,c] fp16
// ---------------------------------------------------------------------------
__global__ __launch_bounds__(256)
void norm_t_kernel(const float* __restrict__ x, const float2* __restrict__ stats,
                   const float* __restrict__ w, const float* __restrict__ bgn,
                   fp16* __restrict__ th)
{
    __shared__ float sm[32][33];
    const int b = blockIdx.z, s0 = blockIdx.x * 32, c0 = blockIdx.y * 32;
    const int tx = threadIdx.x, ty = threadIdx.y;
    #pragma unroll
    for (int cy = ty; cy < 32; cy += 8) {
        const int c = c0 + cy;
        const float2 st = stats[b * 32 + (c >> 4)];
        const float v = x[((size_t)b * CC + c) * SS + s0 + tx];
        sm[cy][tx] = (v - st.x) * st.y * w[c] + bgn[c];
    }
    __syncthreads();
    #pragma unroll
    for (int sy = ty; sy < 32; sy += 8)
        th[((size_t)b * SS + s0 + sy) * CC + c0 + tx] = __float2half(sm[tx][sy]);
}

// ---------------------------------------------------------------------------
// Transpose v [b,s,c] -> vT [b,c,s]
// ---------------------------------------------------------------------------
__global__ __launch_bounds__(256)
void vt_kernel(const fp16* __restrict__ vh, fp16* __restrict__ vth)
{
    __shared__ fp16 sh[32][33];
    const int b = blockIdx.z, s0 = blockIdx.x * 32, c0 = blockIdx.y * 32;
    const int tx = threadIdx.x, ty = threadIdx.y;
    #pragma unroll
    for (int sy = ty; sy < 32; sy += 8)
        sh[sy][tx] = vh[((size_t)b * SS + s0 + sy) * CC + c0 + tx];
    __syncthreads();
    #pragma unroll
    for (int cy = ty; cy < 32; cy += 8)
        vth[((size_t)b * CC + c0 + cy) * SS + s0 + tx] = sh[tx][cy];
}

// ---------------------------------------------------------------------------
// Row softmax over 1024 cols; P -> fp16
// ---------------------------------------------------------------------------
__global__ __launch_bounds__(256)
void softmax_kernel(const float* __restrict__ s, fp16* __restrict__ ph)
{
    const size_t ro = (size_t)blockIdx.x * SS;
    float4 v = *reinterpret_cast<const float4*>(&s[ro + threadIdx.x * 4]);

    float m = fmaxf(fmaxf(v.x, v.y), fmaxf(v.z, v.w));
    #pragma unroll
    for (int o = 16; o; o >>= 1) m = fmaxf(m, __shfl_xor_sync(0xffffffffu, m, o));
    __shared__ float redm[8], reds[8];
    const int lane = threadIdx.x & 31, wid = threadIdx.x >> 5;
    if (lane == 0) redm[wid] = m;
    __syncthreads();
    float M = redm[0];
    #pragma unroll
    for (int i = 1; i < 8; i++) M = fmaxf(M, redm[i]);

    v.x = expf(v.x - M); v.y = expf(v.y - M);
    v.z = expf(v.z - M); v.w = expf(v.w - M);
    float sum = v.x + v.y + v.z + v.w;
    #pragma unroll
    for (int o = 16; o; o >>= 1) sum += __shfl_xor_sync(0xffffffffu, sum, o);
    if (lane == 0) reds[wid] = sum;
    __syncthreads();
    float T = 0.f;
    #pragma unroll
    for (int i = 0; i < 8; i++) T += reds[i];
    const float inv = 1.f / T;

    *reinterpret_cast<__half2*>(&ph[ro + threadIdx.x * 4]) =
        __halves2half2(__float2half(v.x * inv), __float2half(v.y * inv));
    *reinterpret_cast<__half2*>(&ph[ro + threadIdx.x * 4 + 2]) =
        __halves2half2(__float2half(v.z * inv), __float2half(v.w * inv));
}

// ---------------------------------------------------------------------------
// Weight convert fp32 -> fp16
// ---------------------------------------------------------------------------
__global__ __launch_bounds__(256)
void wconv_kernel(const float* __restrict__ src, fp16* __restrict__ dh, int n)
{
    for (int i = blockIdx.x * 256 + threadIdx.x; i < n; i += gridDim.x * 256)
        dh[i] = __float2half(src[i]);
}

// ---------------------------------------------------------------------------
// Final: out[b,c,s] = o2[b,s,c] + x[b,c,s]
// ---------------------------------------------------------------------------
__global__ __launch_bounds__(256)
void transpose_add_kernel(const float* __restrict__ o2, const float* __restrict__ x,
                          float* __restrict__ out)
{
    __shared__ float t[32][33];
    const int b = blockIdx.z, s0 = blockIdx.x * 32, c0 = blockIdx.y * 32;
    #pragma unroll
    for (int i = threadIdx.y; i < 32; i += 8)
        t[i][threadIdx.x] = o2[((size_t)b * SS + s0 + i) * CC + c0 + threadIdx.x];
    __syncthreads();
    #pragma unroll
    for (int i = threadIdx.y; i < 32; i += 8) {
        const size_t idx = ((size_t)b * CC + c0 + i) * SS + s0 + threadIdx.x;
        out[idx] = t[threadIdx.x][i] + x[idx];
    }
}

// ---------------------------------------------------------------------------
// Launch
// ---------------------------------------------------------------------------
extern "C" void kernel_launch(void* const* d_in, const int* in_sizes, int n_in,
                              void* d_out, int out_size)
{
    const float* x   = (const float*)d_in[0];
    const float* gnw = (const float*)d_in[1];
    const float* gnb = (const float*)d_in[2];
    const float* Wq  = (const float*)d_in[3];
    const float* bq  = (const float*)d_in[4];
    const float* Wk  = (const float*)d_in[5];
    const float* bk  = (const float*)d_in[6];
    const float* Wv  = (const float*)d_in[7];
    const float* bv  = (const float*)d_in[8];
    const float* Wo  = (const float*)d_in[9];
    const float* bo  = (const float*)d_in[10];
    float* out = (float*)d_out;

    float2* stats; fp16 *th, *qh, *kh, *vh, *vth, *ph, *oh, *wh;
    float *sc, *o2;
    cudaGetSymbolAddress((void**)&stats, g_stats);
    cudaGetSymbolAddress((void**)&th,  g_th);
    cudaGetSymbolAddress((void**)&qh,  g_qh);
    cudaGetSymbolAddress((void**)&kh,  g_kh);
    cudaGetSymbolAddress((void**)&vh,  g_vh);
    cudaGetSymbolAddress((void**)&vth, g_vth);
    cudaGetSymbolAddress((void**)&sc,  g_s);
    cudaGetSymbolAddress((void**)&ph,  g_ph);
    cudaGetSymbolAddress((void**)&oh,  g_oh);
    cudaGetSymbolAddress((void**)&o2,  g_o2);
    cudaGetSymbolAddress((void**)&wh,  g_wh);

    const int SMEM = 3 * STAGE_B;   // 61440 B
    cudaFuncSetAttribute(gemm_mma<0>, cudaFuncAttributeMaxDynamicSharedMemorySize, SMEM);
    cudaFuncSetAttribute(gemm_mma<1>, cudaFuncAttributeMaxDynamicSharedMemorySize, SMEM);

    const long long sSC = (long long)SS * CC;
    const long long sSS = (long long)SS * SS;

    // 0) weight converts
    wconv_kernel<<<64, 256>>>(Wq, wh + 0 * CC * CC, CC * CC);
    wconv_kernel<<<64, 256>>>(Wk, wh + 1 * CC * CC, CC * CC);
    wconv_kernel<<<64, 256>>>(Wv, wh + 2 * CC * CC, CC * CC);
    wconv_kernel<<<64, 256>>>(Wo, wh + 3 * CC * CC, CC * CC);

    // 1) GroupNorm stats + normalize/transpose -> t [B,S,C] fp16
    gn_stats_kernel<<<BB * NGRP, 256>>>(x, stats);
    norm_t_kernel<<<dim3(SS / 32, CC / 32, BB), dim3(32, 8)>>>(x, stats, gnw, gnb, th);

    // 2) QKV projections (fp16 out)
    dim3 gqkv(CC / 128, SS / 128, BB);
    gemm_mma<1><<<gqkv, 256, SMEM>>>(th, wh + 0 * CC * CC, bq, nullptr, qh,
                                     CC, CC, CC, CC, sSC, 0, sSC, 1.f);
    gemm_mma<1><<<gqkv, 256, SMEM>>>(th, wh + 1 * CC * CC, bk, nullptr, kh,
                                     CC, CC, CC, CC, sSC, 0, sSC, 1.f);
    gemm_mma<1><<<gqkv, 256, SMEM>>>(th, wh + 2 * CC * CC, bv, nullptr, vh,
                                     CC, CC, CC, CC, sSC, 0, sSC, 1.f);

    // 3) v -> vT [B,C,S]
    vt_kernel<<<dim3(SS / 32, CC / 32, BB), dim3(32, 8)>>>(vh, vth);

    // 4) scores = SCALE * q k^T (fp32 out)
    dim3 gsc(SS / 128, SS / 128, BB);
    gemm_mma<0><<<gsc, 256, SMEM>>>(qh, kh, nullptr, sc, nullptr,
                                    CC, CC, CC, SS, sSC, sSC, sSS, SCALE_QK);

    // 5) softmax -> P fp16
    softmax_kernel<<<BB * SS, 256>>>(sc, ph);

    // 6) o = P v (fp16 out)
    dim3 gpv(CC / 128, SS / 128, BB);
    gemm_mma<1><<<gpv, 256, SMEM>>>(ph, vth, nullptr, nullptr, oh,
                                    SS, SS, SS, CC, sSS, sSC, sSC, 1.f);

    // 7) o2 = o Wo^T + bo (fp32 out)
    gemm_mma<0><<<gpv, 256, SMEM>>>(oh, wh + 3 * CC * CC, bo, o2, nullptr,
                                    CC, CC, CC, CC, sSC, 0, sSC, 1.f);

    // 8) out = o2^T + x
    transpose_add_kernel<<<dim3(SS / 32, CC / 32, BB), dim3(32, 8)>>>(o2, x, out);
}

// round 7
// speedup vs baseline: 5.5973x; 1.1752x over previous
#include <cuda_runtime.h>
#include <cuda_fp16.h>
#include <math.h>
#include <stdint.h>

// ---------------------------------------------------------------------------
// AttnBlock via mma.sync HMMA (base sm_100 target).
// Single-pass fp16 GEMMs, fp32 accum. Transposed outputs + residual fused
// into GEMM epilogues (smem-staged); all 4 weight converts in one launch.
// ---------------------------------------------------------------------------

#define BB   32
#define CC   512
#define SS   1024
#define NGRP 32
#define CPG  16
#define GELEMS (CPG * SS)
#define SCALE_QK 0.044194173824159216f

typedef __half fp16;

// ------------------------------- scratch ----------------------------------
static __device__ float2 g_stats[BB * NGRP];
static __device__ fp16 g_th [(size_t)BB * SS * CC];
static __device__ fp16 g_qh [(size_t)BB * SS * CC];
static __device__ fp16 g_kh [(size_t)BB * SS * CC];
static __device__ fp16 g_vth[(size_t)BB * CC * SS];
static __device__ float g_s [(size_t)BB * SS * SS];
static __device__ fp16 g_ph [(size_t)BB * SS * SS];
static __device__ fp16 g_oh [(size_t)BB * SS * CC];
static __device__ fp16 g_wh [4 * CC * CC];

// ------------------------------ asm helpers --------------------------------
__device__ __forceinline__ uint32_t smem_u32(const void* p) {
    uint32_t a;
    asm("{ .reg .u64 t; cvta.to.shared.u64 t, %1; cvt.u32.u64 %0, t; }" : "=r"(a) : "l"(p));
    return a;
}
#define CP16(dst, src) \
    asm volatile("cp.async.cg.shared.global [%0], [%1], 16;" :: "r"(dst), "l"(src))
#define CP_COMMIT() asm volatile("cp.async.commit_group;" ::: "memory")
#define CP_WAIT(n)  asm volatile("cp.async.wait_group %0;" :: "n"(n) : "memory")

#define LDSM4(r0, r1, r2, r3, addr) \
    asm volatile("ldmatrix.sync.aligned.m8n8.x4.shared.b16 {%0,%1,%2,%3}, [%4];" \
        : "=r"(r0), "=r"(r1), "=r"(r2), "=r"(r3) : "r"(addr))

#define MMA_FP16(d, a, b) \
    asm volatile("mma.sync.aligned.m16n8k16.row.col.f32.f16.f16.f32 " \
        "{%0,%1,%2,%3}, {%4,%5,%6,%7}, {%8,%9}, {%0,%1,%2,%3};" \
        : "+f"((d)[0]), "+f"((d)[1]), "+f"((d)[2]), "+f"((d)[3]) \
        : "r"((a)[0]), "r"((a)[1]), "r"((a)[2]), "r"((a)[3]), \
          "r"((b)[0]), "r"((b)[1]))

// ---------------------------------------------------------------------------
// Warp-MMA batched GEMM: C[m,n] = alpha*(A[m,:] . B[n,:]) + bias[n]
// A [M,K] row-major fp16, B [N,K] row-major fp16. CTA tile 128x128, BK=32,
// 8 warps (4x2), warp tile 32x64. 3-stage cp.async pipeline, 2 CTAs/SM.
// OUT_MODE 0: fp32 C[m,n] -> Cf
// OUT_MODE 1: fp16 C[m,n] -> Ch
// OUT_MODE 2: fp16 C^T[n,m] -> Ch           (ldc strides the n dim)
// OUT_MODE 3: fp32 C^T[n,m] + resid -> Cf   (residual add, ldc strides n)
// ---------------------------------------------------------------------------
#define STAGE_B 20480

template<int OUT_MODE>
__global__ void __launch_bounds__(256, 2)
gemm_mma(const fp16* __restrict__ A, const fp16* __restrict__ B,
         const float* __restrict__ bias, const float* __restrict__ resid,
         float* __restrict__ Cf, fp16* __restrict__ Ch,
         int K, int lda, int ldb, int ldc,
         long long sA, long long sB, long long sC, float alpha)
{
    extern __shared__ __align__(16) char smem[];
    const uint32_t sb = smem_u32(smem);
    const int tid = threadIdx.x, wid = tid >> 5, lane = tid & 31;
    const int bm = blockIdx.y * 128, bn = blockIdx.x * 128;

    A += (size_t)blockIdx.z * sA;
    B += (size_t)blockIdx.z * sB;

    const int lrow = tid >> 2;
    const int lseg = tid & 3;

    float acc[2][8][4];
    #pragma unroll
    for (int i = 0; i < 2; i++)
        #pragma unroll
        for (int j = 0; j < 8; j++)
            #pragma unroll
            for (int t = 0; t < 4; t++) acc[i][j][t] = 0.f;

    auto load_stage = [&](int k0, int buf) {
        const uint32_t base = sb + buf * STAGE_B;
        #pragma unroll
        for (int half = 0; half < 2; half++) {
            const int r = lrow + half * 64;
            const uint32_t doff = (uint32_t)(r * 80 + lseg * 16);
            CP16(base +         doff, A + (size_t)(bm + r) * lda + k0 + lseg * 8);
            CP16(base + 10240 + doff, B + (size_t)(bn + r) * ldb + k0 + lseg * 8);
        }
    };

    const int m0 = (wid & 3) * 32, n0 = (wid >> 2) * 64;
    const int arow = (lane & 7) + ((lane >> 3) & 1) * 8;
    const int acol = (lane >> 4) * 8;
    const int brow = (lane & 7) + (lane >> 4) * 8;
    const int bcol = ((lane >> 3) & 1) * 8;

    const int NC = K >> 5;
    load_stage(0, 0);
    CP_COMMIT();
    if (NC > 1) { load_stage(32, 1); CP_COMMIT(); }

    for (int c = 0; c < NC; c++) {
        if (c + 1 < NC) { CP_WAIT(1); } else { CP_WAIT(0); }
        __syncthreads();
        if (c + 2 < NC) {
            load_stage((c + 2) << 5, (c + 2) % 3);
            CP_COMMIT();
        }

        const uint32_t st = sb + (c % 3) * STAGE_B;
        #pragma unroll
        for (int kx = 0; kx < 32; kx += 16) {
            uint32_t fa[2][4];
            uint32_t fb[8][2];
            #pragma unroll
            for (int mt = 0; mt < 2; mt++) {
                const uint32_t ad = st +
                    (uint32_t)(((m0 + mt * 16 + arow) * 40 + kx + acol) * 2);
                LDSM4(fa[mt][0], fa[mt][1], fa[mt][2], fa[mt][3], ad);
            }
            #pragma unroll
            for (int p = 0; p < 4; p++) {
                const uint32_t bd = st + 10240 +
                    (uint32_t)(((n0 + p * 16 + brow) * 40 + kx + bcol) * 2);
                LDSM4(fb[2*p][0], fb[2*p][1], fb[2*p+1][0], fb[2*p+1][1], bd);
            }
            #pragma unroll
            for (int mt = 0; mt < 2; mt++)
                #pragma unroll
                for (int nt = 0; nt < 8; nt++)
                    MMA_FP16(acc[mt][nt], fa[mt], fb[nt]);
        }
        __syncthreads();
    }

    // ------------------------------ epilogue -------------------------------
    if (OUT_MODE <= 1) {
        #pragma unroll
        for (int mt = 0; mt < 2; mt++) {
            const int gm = bm + m0 + mt * 16 + (lane >> 2);
            #pragma unroll
            for (int nt = 0; nt < 8; nt++) {
                const int gn = bn + n0 + nt * 8 + 2 * (lane & 3);
                const float b0 = bias ? bias[gn]     : 0.f;
                const float b1 = bias ? bias[gn + 1] : 0.f;
                const float* d = acc[mt][nt];
                const float v00 = d[0] * alpha + b0, v01 = d[1] * alpha + b1;
                const float v10 = d[2] * alpha + b0, v11 = d[3] * alpha + b1;
                const size_t r0 = (size_t)blockIdx.z * sC + (size_t)gm * ldc + gn;
                const size_t r1 = r0 + (size_t)8 * ldc;
                if (OUT_MODE == 0) {
                    *reinterpret_cast<float2*>(&Cf[r0]) = make_float2(v00, v01);
                    *reinterpret_cast<float2*>(&Cf[r1]) = make_float2(v10, v11);
                } else {
                    *reinterpret_cast<__half2*>(&Ch[r0]) =
                        __halves2half2(__float2half(v00), __float2half(v01));
                    *reinterpret_cast<__half2*>(&Ch[r1]) =
                        __halves2half2(__float2half(v10), __float2half(v11));
                }
            }
        }
    } else {
        // Transposed epilogue: stage 64 n-rows x 128 m-cols per half in smem,
        // emit coalesced along m (global s).
        float* smt = reinterpret_cast<float*>(smem);      // [64][132] fp32
        const int nhme = wid >> 2;
        #pragma unroll
        for (int nh = 0; nh < 2; nh++) {
            __syncthreads();
            if (nhme == nh) {
                #pragma unroll
                for (int mt = 0; mt < 2; mt++) {
                    const int sl = m0 + mt * 16 + (lane >> 2);
                    #pragma unroll
                    for (int nt = 0; nt < 8; nt++) {
                        const int cl = nt * 8 + 2 * (lane & 3);
                        const float b0 = bias ? bias[bn + nh * 64 + cl]     : 0.f;
                        const float b1 = bias ? bias[bn + nh * 64 + cl + 1] : 0.f;
                        const float* d = acc[mt][nt];
                        smt[cl       * 132 + sl]     = d[0] * alpha + b0;
                        smt[(cl + 1) * 132 + sl]     = d[1] * alpha + b1;
                        smt[cl       * 132 + sl + 8] = d[2] * alpha + b0;
                        smt[(cl + 1) * 132 + sl + 8] = d[3] * alpha + b1;
                    }
                }
            }
            __syncthreads();
            if (OUT_MODE == 2) {
                #pragma unroll
                for (int it = 0; it < 16; it++) {
                    const int idx = tid + it * 256;
                    const int cl = idx >> 6, s2 = (idx & 63) * 2;
                    const size_t o = (size_t)blockIdx.z * sC +
                        (size_t)(bn + nh * 64 + cl) * ldc + bm + s2;
                    *reinterpret_cast<__half2*>(&Ch[o]) = __halves2half2(
                        __float2half(smt[cl * 132 + s2]),
                        __float2half(smt[cl * 132 + s2 + 1]));
                }
            } else {
                #pragma unroll
                for (int it = 0; it < 32; it++) {
                    const int idx = tid + it * 256;
                    const int cl = idx >> 7, sl = idx & 127;
                    const size_t o = (size_t)blockIdx.z * sC +
                        (size_t)(bn + nh * 64 + cl) * ldc + bm + sl;
                    Cf[o] = smt[cl * 132 + sl] + resid[o];
                }
            }
        }
    }
}

// ---------------------------------------------------------------------------
// GroupNorm stats
// ---------------------------------------------------------------------------
__global__ __launch_bounds__(256)
void gn_stats_kernel(const float* __restrict__ x, float2* __restrict__ stats)
{
    const int b = blockIdx.x >> 5, g = blockIdx.x & 31;
    const size_t base = ((size_t)b * CC + (size_t)g * CPG) * SS;
    float s = 0.f, s2 = 0.f;
    for (int i = threadIdx.x * 4; i < GELEMS; i += 1024) {
        float4 v = *reinterpret_cast<const float4*>(&x[base + i]);
        s  += v.x + v.y + v.z + v.w;
        s2 += v.x * v.x + v.y * v.y + v.z * v.z + v.w * v.w;
    }
    #pragma unroll
    for (int o = 16; o; o >>= 1) {
        s  += __shfl_xor_sync(0xffffffffu, s, o);
        s2 += __shfl_xor_sync(0xffffffffu, s2, o);
    }
    __shared__ float ws[8], ws2[8];
    if ((threadIdx.x & 31) == 0) { ws[threadIdx.x >> 5] = s; ws2[threadIdx.x >> 5] = s2; }
    __syncthreads();
    if (threadIdx.x == 0) {
        float ts = 0.f, ts2 = 0.f;
        #pragma unroll
        for (int i = 0; i < 8; i++) { ts += ws[i]; ts2 += ws2[i]; }
        const float mu  = ts * (1.f / GELEMS);
        const float var = ts2 * (1.f / GELEMS) - mu * mu;
        stats[blockIdx.x] = make_float2(mu, rsqrtf(var + 1e-6f));
    }
}

// ---------------------------------------------------------------------------
// Normalize + transpose: x[b,c,s] -> t [b,s,c] fp16
// ---------------------------------------------------------------------------
__global__ __launch_bounds__(256)
void norm_t_kernel(const float* __restrict__ x, const float2* __restrict__ stats,
                   const float* __restrict__ w, const float* __restrict__ bgn,
                   fp16* __restrict__ th)
{
    __shared__ float sm[32][33];
    const int b = blockIdx.z, s0 = blockIdx.x * 32, c0 = blockIdx.y * 32;
    const int tx = threadIdx.x, ty = threadIdx.y;
    #pragma unroll
    for (int cy = ty; cy < 32; cy += 8) {
        const int c = c0 + cy;
        const float2 st = stats[b * 32 + (c >> 4)];
        const float v = x[((size_t)b * CC + c) * SS + s0 + tx];
        sm[cy][tx] = (v - st.x) * st.y * w[c] + bgn[c];
    }
    __syncthreads();
    #pragma unroll
    for (int sy = ty; sy < 32; sy += 8)
        th[((size_t)b * SS + s0 + sy) * CC + c0 + tx] = __float2half(sm[tx][sy]);
}

// ---------------------------------------------------------------------------
// Row softmax over 1024 cols; P -> fp16
// ---------------------------------------------------------------------------
__global__ __launch_bounds__(256)
void softmax_kernel(const float* __restrict__ s, fp16* __restrict__ ph)
{
    const size_t ro = (size_t)blockIdx.x * SS;
    float4 v = *reinterpret_cast<const float4*>(&s[ro + threadIdx.x * 4]);

    float m = fmaxf(fmaxf(v.x, v.y), fmaxf(v.z, v.w));
    #pragma unroll
    for (int o = 16; o; o >>= 1) m = fmaxf(m, __shfl_xor_sync(0xffffffffu, m, o));
    __shared__ float redm[8], reds[8];
    const int lane = threadIdx.x & 31, wid = threadIdx.x >> 5;
    if (lane == 0) redm[wid] = m;
    __syncthreads();
    float M = redm[0];
    #pragma unroll
    for (int i = 1; i < 8; i++) M = fmaxf(M, redm[i]);

    v.x = expf(v.x - M); v.y = expf(v.y - M);
    v.z = expf(v.z - M); v.w = expf(v.w - M);
    float sum = v.x + v.y + v.z + v.w;
    #pragma unroll
    for (int o = 16; o; o >>= 1) sum += __shfl_xor_sync(0xffffffffu, sum, o);
    if (lane == 0) reds[wid] = sum;
    __syncthreads();
    float T = 0.f;
    #pragma unroll
    for (int i = 0; i < 8; i++) T += reds[i];
    const float inv = 1.f / T;

    *reinterpret_cast<__half2*>(&ph[ro + threadIdx.x * 4]) =
        __halves2half2(__float2half(v.x * inv), __float2half(v.y * inv));
    *reinterpret_cast<__half2*>(&ph[ro + threadIdx.x * 4 + 2]) =
        __halves2half2(__float2half(v.z * inv), __float2half(v.w * inv));
}

// ---------------------------------------------------------------------------
// All four weight converts in one launch
// ---------------------------------------------------------------------------
__global__ __launch_bounds__(256)
void wconv4_kernel(const float* __restrict__ a, const float* __restrict__ b,
                   const float* __restrict__ c, const float* __restrict__ d,
                   fp16* __restrict__ dst)
{
    const int n = CC * CC;
    for (int i = blockIdx.x * 256 + threadIdx.x; i < n; i += gridDim.x * 256) {
        dst[i]         = __float2half(a[i]);
        dst[n + i]     = __float2half(b[i]);
        dst[2 * n + i] = __float2half(c[i]);
        dst[3 * n + i] = __float2half(d[i]);
    }
}

// ---------------------------------------------------------------------------
// Launch
// ---------------------------------------------------------------------------
extern "C" void kernel_launch(void* const* d_in, const int* in_sizes, int n_in,
                              void* d_out, int out_size)
{
    const float* x   = (const float*)d_in[0];
    const float* gnw = (const float*)d_in[1];
    const float* gnb = (const float*)d_in[2];
    const float* Wq  = (const float*)d_in[3];
    const float* bq  = (const float*)d_in[4];
    const float* Wk  = (const float*)d_in[5];
    const float* bk  = (const float*)d_in[6];
    const float* Wv  = (const float*)d_in[7];
    const float* bv  = (const float*)d_in[8];
    const float* Wo  = (const float*)d_in[9];
    const float* bo  = (const float*)d_in[10];
    float* out = (float*)d_out;

    float2* stats; fp16 *th, *qh, *kh, *vth, *ph, *oh, *wh;
    float *sc;
    cudaGetSymbolAddress((void**)&stats, g_stats);
    cudaGetSymbolAddress((void**)&th,  g_th);
    cudaGetSymbolAddress((void**)&qh,  g_qh);
    cudaGetSymbolAddress((void**)&kh,  g_kh);
    cudaGetSymbolAddress((void**)&vth, g_vth);
    cudaGetSymbolAddress((void**)&sc,  g_s);
    cudaGetSymbolAddress((void**)&ph,  g_ph);
    cudaGetSymbolAddress((void**)&oh,  g_oh);
    cudaGetSymbolAddress((void**)&wh,  g_wh);

    const int SMEM = 3 * STAGE_B;   // 61440 B (>= 64*132*4 epilogue tile)
    cudaFuncSetAttribute(gemm_mma<0>, cudaFuncAttributeMaxDynamicSharedMemorySize, SMEM);
    cudaFuncSetAttribute(gemm_mma<1>, cudaFuncAttributeMaxDynamicSharedMemorySize, SMEM);
    cudaFuncSetAttribute(gemm_mma<2>, cudaFuncAttributeMaxDynamicSharedMemorySize, SMEM);
    cudaFuncSetAttribute(gemm_mma<3>, cudaFuncAttributeMaxDynamicSharedMemorySize, SMEM);

    const long long sSC = (long long)SS * CC;
    const long long sSS = (long long)SS * SS;

    // 0) weight converts (single launch)
    wconv4_kernel<<<256, 256>>>(Wq, Wk, Wv, Wo, wh);

    // 1) GroupNorm stats + normalize/transpose -> t [B,S,C] fp16
    gn_stats_kernel<<<BB * NGRP, 256>>>(x, stats);
    norm_t_kernel<<<dim3(SS / 32, CC / 32, BB), dim3(32, 8)>>>(x, stats, gnw, gnb, th);

    // 2) Q, K projections (fp16 [B,S,C]); V projection written transposed [B,C,S]
    dim3 gqkv(CC / 128, SS / 128, BB);
    gemm_mma<1><<<gqkv, 256, SMEM>>>(th, wh + 0 * CC * CC, bq, nullptr, nullptr, qh,
                                     CC, CC, CC, CC, sSC, 0, sSC, 1.f);
    gemm_mma<1><<<gqkv, 256, SMEM>>>(th, wh + 1 * CC * CC, bk, nullptr, nullptr, kh,
                                     CC, CC, CC, CC, sSC, 0, sSC, 1.f);
    gemm_mma<2><<<gqkv, 256, SMEM>>>(th, wh + 2 * CC * CC, bv, nullptr, nullptr, vth,
                                     CC, CC, CC, SS, sSC, 0, sSC, 1.f);

    // 3) scores = SCALE * q k^T (fp32)
    dim3 gsc(SS / 128, SS / 128, BB);
    gemm_mma<0><<<gsc, 256, SMEM>>>(qh, kh, nullptr, nullptr, sc, nullptr,
                                    CC, CC, CC, SS, sSC, sSC, sSS, SCALE_QK);

    // 4) softmax -> P fp16
    softmax_kernel<<<BB * SS, 256>>>(sc, ph);

    // 5) o = P v (fp16 [B,S,C])
    dim3 gpv(CC / 128, SS / 128, BB);
    gemm_mma<1><<<gpv, 256, SMEM>>>(ph, vth, nullptr, nullptr, nullptr, oh,
                                    SS, SS, SS, CC, sSS, sSC, sSC, 1.f);

    // 6) out[b,c,s] = (o Wo^T + bo)^T + x   (fused transpose + residual)
    gemm_mma<3><<<gpv, 256, SMEM>>>(oh, wh + 3 * CC * CC, bo, x, out, nullptr,
                                    CC, CC, CC, SS, sSC, 0, sSC, 1.f);
}